// round 9
// baseline (speedup 1.0000x reference)
#include <cuda_runtime.h>
#include <cuda_fp16.h>
#include <math.h>
#include <stdint.h>

// ---------------- scratch (static __device__, no allocations) ----------------
__device__ __half g_conv1h[8 * 256 * 64 * 64]; // [b][oc][64*64] fp16
__device__ __half g_wpadh[512 * 8192];         // pc1 weights fp16, K padded 25->32
__device__ __half g_bmat[8 * 900 * 8192];      // im2col matrix [b][sp][k] fp16
__device__ float g_pc1[8 * 512 * 900];         // [b][oc][30*30]
__device__ float g_pc2[8 * 256 * 900];
__device__ float g_pc3[8 * 256 * 784];         // [b][oc][28*28]
__device__ float g_u[8 * 25088 * 8];           // squashed primary caps
__device__ float g_blog[8 * 25088 * 10];       // routing logits
__device__ float g_spart[392 * 1280];          // per-block partial s
__device__ float g_v[1280];
__device__ float g_h1[8 * 512];
__device__ float g_h2[8 * 1024];
__device__ float g_rec[8 * 1296];

__device__ __forceinline__ void mma_fp16_16x8x16(float* d, const uint32_t* a,
                                                 uint32_t b0, uint32_t b1) {
    asm volatile(
        "mma.sync.aligned.m16n8k16.row.col.f32.f16.f16.f32 "
        "{%0,%1,%2,%3}, {%4,%5,%6,%7}, {%8,%9}, {%0,%1,%2,%3};"
        : "+f"(d[0]), "+f"(d[1]), "+f"(d[2]), "+f"(d[3])
        : "r"(a[0]), "r"(a[1]), "r"(a[2]), "r"(a[3]), "r"(b0), "r"(b1));
}
#define LDSM4(r0, r1, r2, r3, addr)                                         \
    asm volatile("ldmatrix.sync.aligned.m8n8.x4.shared.b16 {%0,%1,%2,%3}, [%4];" \
                 : "=r"(r0), "=r"(r1), "=r"(r2), "=r"(r3) : "r"(addr))

// ---------------- conv1: 1->256ch, 9x9, relu, fp16 out (register-tiled) ----------------
__global__ void conv1_kernel(const float* __restrict__ x,
                             const float* __restrict__ w,
                             const float* __restrict__ bias,
                             __half* __restrict__ out) {
    int oc = blockIdx.x, b = blockIdx.y;
    __shared__ float xs[72 * 72];
    __shared__ float wsh[81];
    for (int i = threadIdx.x; i < 5184; i += 256) xs[i] = x[b * 5184 + i];
    if (threadIdx.x < 81) wsh[threadIdx.x] = w[oc * 81 + threadIdx.x];
    __syncthreads();
    float bv = bias[oc];
    int og = threadIdx.x & 7;
    int r0 = threadIdx.x >> 3;
    __half* ob = out + ((size_t)(b * 256 + oc)) * 4096;
    for (int hf = 0; hf < 2; hf++) {
        int oh = r0 + hf * 32;
        int ow0 = og * 8;
        float acc[8];
#pragma unroll
        for (int o = 0; o < 8; o++) acc[o] = bv;
#pragma unroll
        for (int kh = 0; kh < 9; kh++) {
            const float* row = &xs[(oh + kh) * 72 + ow0];
            float seg[16];
#pragma unroll
            for (int s = 0; s < 16; s += 4) {
                float4 v = *(const float4*)&row[s];
                seg[s] = v.x; seg[s + 1] = v.y; seg[s + 2] = v.z; seg[s + 3] = v.w;
            }
#pragma unroll
            for (int kw = 0; kw < 9; kw++) {
                float wv = wsh[kh * 9 + kw];
#pragma unroll
                for (int o = 0; o < 8; o++) acc[o] += seg[kw + o] * wv;
            }
        }
#pragma unroll
        for (int o = 0; o < 8; o++)
            ob[oh * 64 + ow0 + o] = __float2half(fmaxf(acc[o], 0.f));
    }
}

// ---------------- pc1 weight prep: pad 25->32, cvt fp16 (natural k order) ----------------
__global__ void wpad_kernel(const float* __restrict__ w, __half* __restrict__ wp) {
    int idx = blockIdx.x * 256 + threadIdx.x;
    if (idx >= 512 * 8192) return;
    int oc = idx >> 13, r = idx & 8191, ic = r >> 5, k = r & 31;
    float v = (k < 25) ? w[oc * 6400 + ic * 25 + k] : 0.f;
    wp[idx] = __float2half(v);
}

// ---------------- im2col: conv1h -> Bmat[b][sp][k], k padded 25->32 per ic ----------------
__global__ void im2col_kernel(const __half* __restrict__ ch, __half* __restrict__ bm) {
    int oh = blockIdx.x, icc = blockIdx.y, b = blockIdx.z;
    __shared__ __half sx[64 * 324];
    const __half* src = ch + ((size_t)(b * 256 + icc * 64)) * 4096 + (2 * oh) * 64;
    for (int idx = threadIdx.x; idx < 5120; idx += 256) {
        int c4 = idx & 15;
        int r = (idx >> 4) % 5;
        int ic = idx / 80;
        *(uint2*)&sx[ic * 324 + r * 64 + c4 * 4] =
            *(const uint2*)&src[(size_t)ic * 4096 + r * 64 + c4 * 4];
    }
    __syncthreads();
    __half* dstb = bm + ((size_t)b * 900 + oh * 30) * 8192 + icc * 64 * 32;
    for (int idx = threadIdx.x; idx < 1920; idx += 256) {
        int ic = idx & 63, ow = idx >> 6;
        __half hv[32];
#pragma unroll
        for (int e = 0; e < 25; e++)
            hv[e] = sx[ic * 324 + (e / 5) * 64 + 2 * ow + (e % 5)];
#pragma unroll
        for (int e = 25; e < 32; e++) hv[e] = __half(0.f);
        uint32_t pk[16];
#pragma unroll
        for (int t = 0; t < 16; t++) {
            __half2 p = __halves2half2(hv[2 * t], hv[2 * t + 1]);
            pk[t] = *(uint32_t*)&p;
        }
        uint4* dst = (uint4*)(dstb + (size_t)ow * 8192 + ic * 32);
        dst[0] = make_uint4(pk[0], pk[1], pk[2], pk[3]);
        dst[1] = make_uint4(pk[4], pk[5], pk[6], pk[7]);
        dst[2] = make_uint4(pk[8], pk[9], pk[10], pk[11]);
        dst[3] = make_uint4(pk[12], pk[13], pk[14], pk[15]);
    }
}

// ---------------- pc1 via mma.sync fp16 m16n8k16, ldmatrix + double-buffer ----------------
#define ASTR 40  // halves per row (80B) -> conflict-free ldmatrix rows
__global__ void __launch_bounds__(256, 2)
pc1_mma_kernel(const __half* __restrict__ bmat, const uint2* __restrict__ wph2,
               const float* __restrict__ bias, float* __restrict__ out) {
    __shared__ __half As[2][128 * ASTR];
    __shared__ __half Bs[2][128 * ASTR];
    const int tid = threadIdx.x;
    const int lane = tid & 31, wid = tid >> 5;
    const int spt = blockIdx.x, oct = blockIdx.y, b = blockIdx.z;
    const int oc_base = oct * 128, sp_base = spt * 128;
    const int wm = wid & 3, wn = wid >> 2;

    // producer geometry
    const int rr = tid >> 3, grp = tid & 7;
    const uint2* bb[4];
    int bval[4];
#pragma unroll
    for (int q = 0; q < 4; q++) {
        int sp = sp_base + 32 * q + rr;
        bval[q] = (sp < 900);
        bb[q] = (const uint2*)(bmat + ((size_t)b * 900 + (bval[q] ? sp : 0)) * 8192) + grp;
    }
    const uint2* wbase = wph2 + (size_t)oc_base * 2048;

    float acc[2][8][4];
#pragma unroll
    for (int mt = 0; mt < 2; mt++)
#pragma unroll
        for (int nt = 0; nt < 8; nt++)
#pragma unroll
            for (int i = 0; i < 4; i++) acc[mt][nt][i] = 0.f;

    // ldmatrix per-lane address offsets (in halves)
    const int l15 = lane & 15;
    uint32_t a_off[2];
#pragma unroll
    for (int mt = 0; mt < 2; mt++)
        a_off[mt] = (uint32_t)(((wm * 2 + mt) * 16 + l15) * ASTR + ((lane >> 4) & 1) * 8);
    uint32_t b_off[4];
#pragma unroll
    for (int p = 0; p < 4; p++)
        b_off[p] = (uint32_t)((((wn * 8 + 2 * p + ((lane >> 4) & 1)) * 8) + (lane & 7)) * ASTR +
                              ((lane >> 3) & 1) * 8);
    uint32_t aBase[2], bBase[2];
#pragma unroll
    for (int bi = 0; bi < 2; bi++) {
        aBase[bi] = (uint32_t)__cvta_generic_to_shared(&As[bi][0]);
        bBase[bi] = (uint32_t)__cvta_generic_to_shared(&Bs[bi][0]);
    }

    uint2 aR[4], bR[4];
    const uint2 z2 = make_uint2(0u, 0u);
#pragma unroll
    for (int q = 0; q < 4; q++)
        aR[q] = wbase[(size_t)(32 * q + rr) * 2048 + grp];
#pragma unroll
    for (int q = 0; q < 4; q++)
        bR[q] = bval[q] ? bb[q][0] : z2;

    for (int ic = 0; ic < 256; ic++) {
        const int bi = ic & 1;
#pragma unroll
        for (int q = 0; q < 4; q++)
            *(uint2*)&As[bi][(32 * q + rr) * ASTR + grp * 4] = aR[q];
#pragma unroll
        for (int q = 0; q < 4; q++)
            *(uint2*)&Bs[bi][(32 * q + rr) * ASTR + grp * 4] = bR[q];
        if (ic + 1 < 256) {
#pragma unroll
            for (int q = 0; q < 4; q++)
                aR[q] = wbase[(size_t)(32 * q + rr) * 2048 + (ic + 1) * 8 + grp];
#pragma unroll
            for (int q = 0; q < 4; q++)
                bR[q] = bval[q] ? bb[q][(ic + 1) * 8] : z2;
        }
        __syncthreads();
#pragma unroll
        for (int k16 = 0; k16 < 2; k16++) {
            const uint32_t kadd = k16 * 32;  // bytes (16 halves)
            uint32_t afr[2][4];
            LDSM4(afr[0][0], afr[0][1], afr[0][2], afr[0][3], aBase[bi] + a_off[0] * 2 + kadd);
            LDSM4(afr[1][0], afr[1][1], afr[1][2], afr[1][3], aBase[bi] + a_off[1] * 2 + kadd);
#pragma unroll
            for (int p = 0; p < 4; p++) {
                uint32_t b0, b1, b2, b3;
                LDSM4(b0, b1, b2, b3, bBase[bi] + b_off[p] * 2 + kadd);
                mma_fp16_16x8x16(acc[0][2 * p], afr[0], b0, b1);
                mma_fp16_16x8x16(acc[1][2 * p], afr[1], b0, b1);
                mma_fp16_16x8x16(acc[0][2 * p + 1], afr[0], b2, b3);
                mma_fp16_16x8x16(acc[1][2 * p + 1], afr[1], b2, b3);
            }
        }
    }
    // epilogue
    const int gr = lane >> 2;
    const int c2 = (lane & 3) * 2;
#pragma unroll
    for (int mt = 0; mt < 2; mt++) {
        int oc0 = oc_base + (wm * 2 + mt) * 16 + gr;
        float b0 = bias[oc0], b1 = bias[oc0 + 8];
        float* op0 = out + ((size_t)b * 512 + oc0) * 900;
        float* op1 = out + ((size_t)b * 512 + oc0 + 8) * 900;
#pragma unroll
        for (int nt = 0; nt < 8; nt++) {
            int sp = sp_base + (wn * 8 + nt) * 8 + c2;
            if (sp < 900) {
                *(float2*)&op0[sp] = make_float2(acc[mt][nt][0] + b0, acc[mt][nt][1] + b0);
                *(float2*)&op1[sp] = make_float2(acc[mt][nt][2] + b1, acc[mt][nt][3] + b1);
            }
        }
    }
}

// ---------------- pc2: grouped 32g, 16->8, 3x3, pad 1 (3 row slices) ----------------
__global__ void pc2_kernel(const float* __restrict__ in,
                           const float* __restrict__ w,
                           const float* __restrict__ bias,
                           float* __restrict__ out) {
    int g = blockIdx.x, b = blockIdx.y, sl = blockIdx.z;
    int oh0 = sl * 10;
    __shared__ float wsh[1152];
    __shared__ float xin[16 * 12 * 30];
    for (int idx = threadIdx.x; idx < 1152; idx += 256) wsh[idx] = w[g * 1152 + idx];
    const float* inb = in + ((size_t)b * 512 + g * 16) * 900;
    for (int idx = threadIdx.x; idx < 5760; idx += 256) {
        int iw = idx % 30;
        int r2 = idx / 30;
        int ihl = r2 % 12, i = r2 / 12;
        int ih = oh0 - 1 + ihl;
        xin[idx] = (ih >= 0 && ih < 30) ? inb[i * 900 + ih * 30 + iw] : 0.f;
    }
    __syncthreads();
    for (int spl = threadIdx.x; spl < 300; spl += 256) {
        int ohl = spl / 30, ow = spl - ohl * 30;
        int oh = oh0 + ohl;
        float acc[8];
#pragma unroll
        for (int o = 0; o < 8; o++) acc[o] = bias[g * 8 + o];
        for (int i = 0; i < 16; i++) {
            const float* ip = xin + i * 360;
#pragma unroll
            for (int kh = 0; kh < 3; kh++) {
#pragma unroll
                for (int kw = 0; kw < 3; kw++) {
                    int iw = ow - 1 + kw;
                    if (iw < 0 || iw >= 30) continue;
                    float v = ip[(ohl + kh) * 30 + iw];
                    int e = kh * 3 + kw;
#pragma unroll
                    for (int o = 0; o < 8; o++) acc[o] += v * wsh[(o * 16 + i) * 9 + e];
                }
            }
        }
#pragma unroll
        for (int o = 0; o < 8; o++)
            out[((size_t)b * 256 + g * 8 + o) * 900 + oh * 30 + ow] = acc[o];
    }
}

// ---------------- pc3: grouped 32g, 8->8, 3x3, pad 0 (30->28), 4 row slices ----------------
__global__ void pc3_kernel(const float* __restrict__ in,
                           const float* __restrict__ w,
                           const float* __restrict__ bias,
                           float* __restrict__ out) {
    int g = blockIdx.x, b = blockIdx.y, sl = blockIdx.z;
    int oh0 = sl * 7;
    __shared__ float wsh[576];
    __shared__ float xin[8 * 9 * 30];
    for (int idx = threadIdx.x; idx < 576; idx += 256) wsh[idx] = w[g * 576 + idx];
    const float* inb = in + ((size_t)b * 256 + g * 8) * 900;
    for (int idx = threadIdx.x; idx < 2160; idx += 256) {
        int iw = idx % 30;
        int r2 = idx / 30;
        int ihl = r2 % 9, i = r2 / 9;
        xin[idx] = inb[i * 900 + (oh0 + ihl) * 30 + iw];
    }
    __syncthreads();
    for (int spl = threadIdx.x; spl < 196; spl += 256) {
        int ohl = spl / 28, ow = spl - ohl * 28;
        int oh = oh0 + ohl;
        float acc[8];
#pragma unroll
        for (int o = 0; o < 8; o++) acc[o] = bias[g * 8 + o];
        for (int i = 0; i < 8; i++) {
            const float* ip = xin + i * 270;
#pragma unroll
            for (int kh = 0; kh < 3; kh++) {
#pragma unroll
                for (int kw = 0; kw < 3; kw++) {
                    float v = ip[(ohl + kh) * 30 + ow + kw];
                    int e = kh * 3 + kw;
#pragma unroll
                    for (int o = 0; o < 8; o++) acc[o] += v * wsh[(o * 8 + i) * 9 + e];
                }
            }
        }
#pragma unroll
        for (int o = 0; o < 8; o++)
            out[((size_t)b * 256 + g * 8 + o) * 784 + oh * 28 + ow] = acc[o];
    }
}

// ---------------- build u (capsule transpose) + squash over dim 8 ----------------
__global__ void u_build_kernel(const float* __restrict__ y, float* __restrict__ u) {
    int b = blockIdx.y;
    int s0 = blockIdx.x * 16;
    __shared__ float ys[256 * 16];
    for (int i = threadIdx.x; i < 4096; i += 256) {
        int ch = i >> 4, si = i & 15;
        ys[i] = y[(b * 256 + ch) * 784 + s0 + si];
    }
    __syncthreads();
    for (int p = threadIdx.x; p < 512; p += 256) {
        int si = p >> 5, cap = p & 31;
        float d[8];
        float sq = 0.f;
#pragma unroll
        for (int i = 0; i < 8; i++) {
            d[i] = ys[(cap * 8 + i) * 16 + si];
            sq += d[i] * d[i];
        }
        float f = sq / (sqrtf(sq) * (1.f + sq));
        int n = (s0 + si) * 32 + cap;
        float* up = u + ((size_t)b * 25088 + n) * 8;
#pragma unroll
        for (int i = 0; i < 8; i++) up[i] = f * d[i];
    }
}

// ---------------- fused routing pass ----------------
__global__ void routing_kernel(const float* __restrict__ W, int mode) {
    int warp = (blockIdx.x * 256 + threadIdx.x) >> 5;
    int lane = threadIdx.x & 31;
    int bhalf = lane >> 4;
    int j = lane & 15;
    float s_acc[4][10];
#pragma unroll
    for (int bp = 0; bp < 4; bp++)
#pragma unroll
        for (int k = 0; k < 10; k++) s_acc[bp][k] = 0.f;

    int n0 = warp * 8;
    for (int nn = 0; nn < 8; nn++) {
        int n = n0 + nn;
        const float* Wn = W + (size_t)n * 1280;
#pragma unroll
        for (int bp = 0; bp < 4; bp++) {
            int b = bp * 2 + bhalf;
            const float* up = g_u + ((size_t)b * 25088 + n) * 8;
            float uu[8];
#pragma unroll
            for (int i = 0; i < 8; i++) uu[i] = up[i];
            float uh[10];
#pragma unroll
            for (int k = 0; k < 10; k++) {
                float a = 0.f;
#pragma unroll
                for (int i = 0; i < 8; i++) a += uu[i] * Wn[k * 128 + i * 16 + j];
                uh[k] = a;
            }
            float c[10];
            if (mode == 0) {
#pragma unroll
                for (int k = 0; k < 10; k++) c[k] = 0.1f;
            } else {
                float bl[10];
#pragma unroll
                for (int k = 0; k < 10; k++) {
                    float d = uh[k] * g_v[(b * 10 + k) * 16 + j];
                    d += __shfl_xor_sync(0xffffffffu, d, 1);
                    d += __shfl_xor_sync(0xffffffffu, d, 2);
                    d += __shfl_xor_sync(0xffffffffu, d, 4);
                    d += __shfl_xor_sync(0xffffffffu, d, 8);
                    bl[k] = d;
                }
                if (mode == 2) {
#pragma unroll
                    for (int k = 0; k < 10; k++)
                        bl[k] += g_blog[((size_t)b * 25088 + n) * 10 + k];
                } else if (j == 0) {
#pragma unroll
                    for (int k = 0; k < 10; k++)
                        g_blog[((size_t)b * 25088 + n) * 10 + k] = bl[k];
                }
                float m = bl[0];
#pragma unroll
                for (int k = 1; k < 10; k++) m = fmaxf(m, bl[k]);
                float sum = 0.f;
#pragma unroll
                for (int k = 0; k < 10; k++) { c[k] = expf(bl[k] - m); sum += c[k]; }
                float inv = 1.f / sum;
#pragma unroll
                for (int k = 0; k < 10; k++) c[k] *= inv;
            }
#pragma unroll
            for (int k = 0; k < 10; k++) s_acc[bp][k] += c[k] * uh[k];
        }
    }
    __shared__ float ssm[8][1280];
    int wl = (threadIdx.x >> 5);
#pragma unroll
    for (int bp = 0; bp < 4; bp++) {
        int b = bp * 2 + bhalf;
#pragma unroll
        for (int k = 0; k < 10; k++)
            ssm[wl][(b * 10 + k) * 16 + j] = s_acc[bp][k];
    }
    __syncthreads();
    for (int i = threadIdx.x; i < 1280; i += 256) {
        float t = 0.f;
#pragma unroll
        for (int w = 0; w < 8; w++) t += ssm[w][i];
        g_spart[blockIdx.x * 1280 + i] = t;
    }
}

// ---------------- fused reduce + squash ----------------
__global__ void reduce_squash_kernel(float* out_opt) {
    int half = threadIdx.x >> 7;
    int t = threadIdx.x & 127;
    int i = blockIdx.x * 128 + t;  // 10 blocks x 128 = 1280
    float s = 0.f;
    for (int p = half * 196; p < half * 196 + 196; p++) s += g_spart[p * 1280 + i];
    __shared__ float sh[128];
    if (half) sh[t] = s;
    __syncthreads();
    if (!half) {
        s += sh[t];
        float sq = s * s;
        sq += __shfl_xor_sync(0xffffffffu, sq, 1);
        sq += __shfl_xor_sync(0xffffffffu, sq, 2);
        sq += __shfl_xor_sync(0xffffffffu, sq, 4);
        sq += __shfl_xor_sync(0xffffffffu, sq, 8);
        float f = sq / (sqrtf(sq) * (1.f + sq));
        float vv = f * s;
        g_v[i] = vv;
        if (out_opt) out_opt[i] = vv;
    }
}

// ---------------- decoder ----------------
__global__ void fc1_kernel(const float* __restrict__ target,
                           const float* __restrict__ w,
                           const float* __restrict__ bias) {
    int b = blockIdx.x;
    __shared__ float vm[16];
    if (threadIdx.x < 16) {
        float a = 0.f;
        for (int k = 0; k < 10; k++) a += target[b * 10 + k] * g_v[(b * 10 + k) * 16 + threadIdx.x];
        vm[threadIdx.x] = a;
    }
    __syncthreads();
    int o = threadIdx.x;
    float acc = bias[o];
#pragma unroll
    for (int i = 0; i < 16; i++) acc += vm[i] * w[o * 16 + i];
    g_h1[b * 512 + o] = fmaxf(acc, 0.f);
}

// warp-per-output coalesced dot products
__global__ void fc2_kernel(const float* __restrict__ w, const float* __restrict__ bias) {
    int b = blockIdx.x;
    __shared__ float h1[512];
    for (int i = threadIdx.x; i < 512; i += 256) h1[i] = g_h1[b * 512 + i];
    __syncthreads();
    int warp = threadIdx.x >> 5, lane = threadIdx.x & 31;
    for (int o = warp; o < 1024; o += 8) {
        const float* wr = w + (size_t)o * 512;
        float a = 0.f;
#pragma unroll 4
        for (int i = lane; i < 512; i += 32) a += h1[i] * wr[i];
        a += __shfl_xor_sync(0xffffffffu, a, 16);
        a += __shfl_xor_sync(0xffffffffu, a, 8);
        a += __shfl_xor_sync(0xffffffffu, a, 4);
        a += __shfl_xor_sync(0xffffffffu, a, 2);
        a += __shfl_xor_sync(0xffffffffu, a, 1);
        if (lane == 0) g_h2[b * 1024 + o] = fmaxf(a + bias[o], 0.f);
    }
}

__global__ void fc3_kernel(const float* __restrict__ w, const float* __restrict__ bias) {
    int b = blockIdx.x;
    __shared__ float h2[1024];
    for (int i = threadIdx.x; i < 1024; i += 512) h2[i] = g_h2[b * 1024 + i];
    __syncthreads();
    int warp = threadIdx.x >> 5, lane = threadIdx.x & 31;
    for (int o = warp; o < 1296; o += 16) {
        const float* wr = w + (size_t)o * 1024;
        float a = 0.f;
#pragma unroll 4
        for (int i = lane; i < 1024; i += 32) a += h2[i] * wr[i];
        a += __shfl_xor_sync(0xffffffffu, a, 16);
        a += __shfl_xor_sync(0xffffffffu, a, 8);
        a += __shfl_xor_sync(0xffffffffu, a, 4);
        a += __shfl_xor_sync(0xffffffffu, a, 2);
        a += __shfl_xor_sync(0xffffffffu, a, 1);
        if (lane == 0) g_rec[b * 1296 + o] = 1.f / (1.f + expf(-(a + bias[o])));
    }
}

__global__ void upsample_kernel(float* __restrict__ out) {
    int idx = blockIdx.x * 256 + threadIdx.x;
    if (idx >= 8 * 5184) return;
    int b = idx / 5184;
    int r = idx - b * 5184;
    int oy = r / 72, ox = r - oy * 72;
    float sy = (float)(oy * 35) / 71.0f;
    float sx = (float)(ox * 35) / 71.0f;
    int y0 = (int)sy, x0 = (int)sx;
    int y1 = min(y0 + 1, 35), x1 = min(x0 + 1, 35);
    float wy = sy - (float)y0, wx = sx - (float)x0;
    const float* rb = g_rec + b * 1296;
    float a00 = rb[y0 * 36 + x0], a01 = rb[y0 * 36 + x1];
    float a10 = rb[y1 * 36 + x0], a11 = rb[y1 * 36 + x1];
    float v = (1.f - wy) * ((1.f - wx) * a00 + wx * a01) +
              wy * ((1.f - wx) * a10 + wx * a11);
    out[1280 + b * 5184 + r] = v;
}

// ---------------- launch ----------------
extern "C" void kernel_launch(void* const* d_in, const int* in_sizes, int n_in,
                              void* d_out, int out_size) {
    const float* x       = (const float*)d_in[0];
    const float* target  = (const float*)d_in[1];
    const float* conv1_w = (const float*)d_in[2];
    const float* conv1_b = (const float*)d_in[3];
    const float* pc1_w   = (const float*)d_in[4];
    const float* pc1_b   = (const float*)d_in[5];
    const float* pc2_w   = (const float*)d_in[6];
    const float* pc2_b   = (const float*)d_in[7];
    const float* pc3_w   = (const float*)d_in[8];
    const float* pc3_b   = (const float*)d_in[9];
    const float* W_digit = (const float*)d_in[10];
    const float* fc1_w   = (const float*)d_in[11];
    const float* fc1_b   = (const float*)d_in[12];
    const float* fc2_w   = (const float*)d_in[13];
    const float* fc2_b   = (const float*)d_in[14];
    const float* fc3_w   = (const float*)d_in[15];
    const float* fc3_b   = (const float*)d_in[16];
    float* out = (float*)d_out;

    float *pc1p, *pc2p, *pc3p, *up;
    __half *conv1p, *wpp, *bmp;
    cudaGetSymbolAddress((void**)&conv1p, g_conv1h);
    cudaGetSymbolAddress((void**)&wpp, g_wpadh);
    cudaGetSymbolAddress((void**)&bmp, g_bmat);
    cudaGetSymbolAddress((void**)&pc1p, g_pc1);
    cudaGetSymbolAddress((void**)&pc2p, g_pc2);
    cudaGetSymbolAddress((void**)&pc3p, g_pc3);
    cudaGetSymbolAddress((void**)&up, g_u);

    conv1_kernel<<<dim3(256, 8), 256>>>(x, conv1_w, conv1_b, conv1p);
    wpad_kernel<<<16384, 256>>>(pc1_w, wpp);
    im2col_kernel<<<dim3(30, 4, 8), 256>>>(conv1p, bmp);
    pc1_mma_kernel<<<dim3(8, 4, 8), 256>>>(bmp, (const uint2*)wpp, pc1_b, pc1p);
    pc2_kernel<<<dim3(32, 8, 3), 256>>>(pc1p, pc2_w, pc2_b, pc2p);
    pc3_kernel<<<dim3(32, 8, 4), 256>>>(pc2p, pc3_w, pc3_b, pc3p);
    u_build_kernel<<<dim3(49, 8), 256>>>(pc3p, up);

    // routing
    routing_kernel<<<392, 256>>>(W_digit, 0);
    reduce_squash_kernel<<<10, 256>>>(nullptr);
    routing_kernel<<<392, 256>>>(W_digit, 1);
    reduce_squash_kernel<<<10, 256>>>(nullptr);
    routing_kernel<<<392, 256>>>(W_digit, 2);
    reduce_squash_kernel<<<10, 256>>>(out);

    // decoder
    fc1_kernel<<<8, 512>>>(target, fc1_w, fc1_b);
    fc2_kernel<<<8, 256>>>(fc2_w, fc2_b);
    fc3_kernel<<<8, 512>>>(fc3_w, fc3_b);
    upsample_kernel<<<162, 256>>>(out);
}

// round 10
// speedup vs baseline: 1.5766x; 1.5766x over previous
#include <cuda_runtime.h>
#include <cuda_fp16.h>
#include <math.h>
#include <stdint.h>

// ---------------- scratch (static __device__, no allocations) ----------------
__device__ __half g_conv1h[8 * 256 * 64 * 64]; // [b][oc][64*64] fp16
__device__ __half g_wpadh[512 * 8192];         // pc1 weights fp16, K padded 25->32
__device__ __half g_bmat[8 * 900 * 8192];      // im2col matrix [b][sp][k] fp16
__device__ float g_pc1[8 * 512 * 900];         // [b][oc][30*30]
__device__ float g_pc2[8 * 256 * 900];
__device__ float g_pc3[8 * 256 * 784];         // [b][oc][28*28]
__device__ float g_u[8 * 25088 * 8];           // squashed primary caps
__device__ float g_blog[8 * 25088 * 10];       // routing logits
__device__ float g_spart[392 * 1280];          // per-block partial s
__device__ float g_v[1280];
__device__ float g_h1[8 * 512];
__device__ float g_h2[8 * 1024];
__device__ float g_rec[8 * 1296];

__device__ __forceinline__ void mma_fp16_16x8x16(float* d, const uint32_t* a,
                                                 uint32_t b0, uint32_t b1) {
    asm volatile(
        "mma.sync.aligned.m16n8k16.row.col.f32.f16.f16.f32 "
        "{%0,%1,%2,%3}, {%4,%5,%6,%7}, {%8,%9}, {%0,%1,%2,%3};"
        : "+f"(d[0]), "+f"(d[1]), "+f"(d[2]), "+f"(d[3])
        : "r"(a[0]), "r"(a[1]), "r"(a[2]), "r"(a[3]), "r"(b0), "r"(b1));
}
#define LDSM4(r0, r1, r2, r3, addr)                                         \
    asm volatile("ldmatrix.sync.aligned.m8n8.x4.shared.b16 {%0,%1,%2,%3}, [%4];" \
                 : "=r"(r0), "=r"(r1), "=r"(r2), "=r"(r3) : "r"(addr))

// ---------------- conv1: 1->256ch, 9x9, relu, fp16 out (register-tiled) ----------------
__global__ void conv1_kernel(const float* __restrict__ x,
                             const float* __restrict__ w,
                             const float* __restrict__ bias,
                             __half* __restrict__ out) {
    int oc = blockIdx.x, b = blockIdx.y;
    __shared__ float xs[72 * 72];
    __shared__ float wsh[81];
    for (int i = threadIdx.x; i < 5184; i += 256) xs[i] = x[b * 5184 + i];
    if (threadIdx.x < 81) wsh[threadIdx.x] = w[oc * 81 + threadIdx.x];
    __syncthreads();
    float bv = bias[oc];
    int og = threadIdx.x & 7;
    int r0 = threadIdx.x >> 3;
    __half* ob = out + ((size_t)(b * 256 + oc)) * 4096;
    for (int hf = 0; hf < 2; hf++) {
        int oh = r0 + hf * 32;
        int ow0 = og * 8;
        float acc[8];
#pragma unroll
        for (int o = 0; o < 8; o++) acc[o] = bv;
#pragma unroll
        for (int kh = 0; kh < 9; kh++) {
            const float* row = &xs[(oh + kh) * 72 + ow0];
            float seg[16];
#pragma unroll
            for (int s = 0; s < 16; s += 4) {
                float4 v = *(const float4*)&row[s];
                seg[s] = v.x; seg[s + 1] = v.y; seg[s + 2] = v.z; seg[s + 3] = v.w;
            }
#pragma unroll
            for (int kw = 0; kw < 9; kw++) {
                float wv = wsh[kh * 9 + kw];
#pragma unroll
                for (int o = 0; o < 8; o++) acc[o] += seg[kw + o] * wv;
            }
        }
#pragma unroll
        for (int o = 0; o < 8; o++)
            ob[oh * 64 + ow0 + o] = __float2half(fmaxf(acc[o], 0.f));
    }
}

// ---------------- pc1 weight prep: pad 25->32, cvt fp16 (natural k order) ----------------
__global__ void wpad_kernel(const float* __restrict__ w, __half* __restrict__ wp) {
    int idx = blockIdx.x * 256 + threadIdx.x;
    if (idx >= 512 * 8192) return;
    int oc = idx >> 13, r = idx & 8191, ic = r >> 5, k = r & 31;
    float v = (k < 25) ? w[oc * 6400 + ic * 25 + k] : 0.f;
    wp[idx] = __float2half(v);
}

// ---------------- im2col: conv1h -> Bmat[b][sp][k], k padded 25->32 per ic ----------------
__global__ void im2col_kernel(const __half* __restrict__ ch, __half* __restrict__ bm) {
    int oh = blockIdx.x, icc = blockIdx.y, b = blockIdx.z;
    __shared__ __half sx[64 * 324];
    const __half* src = ch + ((size_t)(b * 256 + icc * 64)) * 4096 + (2 * oh) * 64;
    for (int idx = threadIdx.x; idx < 5120; idx += 256) {
        int c4 = idx & 15;
        int r = (idx >> 4) % 5;
        int ic = idx / 80;
        *(uint2*)&sx[ic * 324 + r * 64 + c4 * 4] =
            *(const uint2*)&src[(size_t)ic * 4096 + r * 64 + c4 * 4];
    }
    __syncthreads();
    __half* dstb = bm + ((size_t)b * 900 + oh * 30) * 8192 + icc * 64 * 32;
    for (int idx = threadIdx.x; idx < 1920; idx += 256) {
        int ic = idx & 63, ow = idx >> 6;
        __half hv[32];
#pragma unroll
        for (int e = 0; e < 25; e++)
            hv[e] = sx[ic * 324 + (e / 5) * 64 + 2 * ow + (e % 5)];
#pragma unroll
        for (int e = 25; e < 32; e++) hv[e] = __half(0.f);
        uint32_t pk[16];
#pragma unroll
        for (int t = 0; t < 16; t++) {
            __half2 p = __halves2half2(hv[2 * t], hv[2 * t + 1]);
            pk[t] = *(uint32_t*)&p;
        }
        uint4* dst = (uint4*)(dstb + (size_t)ow * 8192 + ic * 32);
        dst[0] = make_uint4(pk[0], pk[1], pk[2], pk[3]);
        dst[1] = make_uint4(pk[4], pk[5], pk[6], pk[7]);
        dst[2] = make_uint4(pk[8], pk[9], pk[10], pk[11]);
        dst[3] = make_uint4(pk[12], pk[13], pk[14], pk[15]);
    }
}

// ---------------- pc1 via mma.sync fp16 m16n8k16, ldmatrix + uint4 producer ----------------
#define ASTR 40  // halves per row (80B) -> conflict-free ldmatrix rows
__global__ void __launch_bounds__(256, 2)
pc1_mma_kernel(const __half* __restrict__ bmat, const uint4* __restrict__ wph4,
               const float* __restrict__ bias, float* __restrict__ out) {
    __shared__ __align__(16) __half As[2][128 * ASTR];
    __shared__ __align__(16) __half Bs[2][128 * ASTR];
    const int tid = threadIdx.x;
    const int lane = tid & 31, wid = tid >> 5;
    const int spt = blockIdx.x, oct = blockIdx.y, b = blockIdx.z;
    const int oc_base = oct * 128, sp_base = spt * 128;
    const int wm = wid & 3, wn = wid >> 2;

    // producer geometry: thread covers rows rr2, rr2+64 at 16B group grp4
    const int grp4 = tid & 3;
    const int rr2 = tid >> 2;  // 0..63
    const uint4* bb[2];
    int bval[2];
#pragma unroll
    for (int q = 0; q < 2; q++) {
        int sp = sp_base + rr2 + 64 * q;
        bval[q] = (sp < 900);
        bb[q] = (const uint4*)(bmat + ((size_t)b * 900 + (bval[q] ? sp : 0)) * 8192) + grp4;
    }
    const uint4* wbase = wph4 + (size_t)oc_base * 1024 + grp4;

    float acc[2][8][4];
#pragma unroll
    for (int mt = 0; mt < 2; mt++)
#pragma unroll
        for (int nt = 0; nt < 8; nt++)
#pragma unroll
            for (int i = 0; i < 4; i++) acc[mt][nt][i] = 0.f;

    // ldmatrix per-lane address offsets (in halves)
    const int l15 = lane & 15;
    uint32_t a_off[2];
#pragma unroll
    for (int mt = 0; mt < 2; mt++)
        a_off[mt] = (uint32_t)(((wm * 2 + mt) * 16 + l15) * ASTR + ((lane >> 4) & 1) * 8);
    uint32_t b_off[4];
#pragma unroll
    for (int p = 0; p < 4; p++)
        b_off[p] = (uint32_t)((((wn * 8 + 2 * p + ((lane >> 4) & 1)) * 8) + (lane & 7)) * ASTR +
                              ((lane >> 3) & 1) * 8);
    uint32_t aBase[2], bBase[2];
#pragma unroll
    for (int bi = 0; bi < 2; bi++) {
        aBase[bi] = (uint32_t)__cvta_generic_to_shared(&As[bi][0]);
        bBase[bi] = (uint32_t)__cvta_generic_to_shared(&Bs[bi][0]);
    }

    uint4 aR[2], bR[2];
    const uint4 z4 = make_uint4(0u, 0u, 0u, 0u);
#pragma unroll
    for (int q = 0; q < 2; q++)
        aR[q] = wbase[(size_t)(rr2 + 64 * q) * 1024];
#pragma unroll
    for (int q = 0; q < 2; q++)
        bR[q] = bval[q] ? bb[q][0] : z4;

    for (int ic = 0; ic < 256; ic++) {
        const int bi = ic & 1;
#pragma unroll
        for (int q = 0; q < 2; q++)
            *(uint4*)&As[bi][(rr2 + 64 * q) * ASTR + grp4 * 8] = aR[q];
#pragma unroll
        for (int q = 0; q < 2; q++)
            *(uint4*)&Bs[bi][(rr2 + 64 * q) * ASTR + grp4 * 8] = bR[q];
        if (ic + 1 < 256) {
#pragma unroll
            for (int q = 0; q < 2; q++)
                aR[q] = wbase[(size_t)(rr2 + 64 * q) * 1024 + (ic + 1) * 4];
#pragma unroll
            for (int q = 0; q < 2; q++)
                bR[q] = bval[q] ? bb[q][(ic + 1) * 4] : z4;
        }
        __syncthreads();
#pragma unroll
        for (int k16 = 0; k16 < 2; k16++) {
            const uint32_t kadd = k16 * 32;  // bytes (16 halves)
            uint32_t afr[2][4];
            LDSM4(afr[0][0], afr[0][1], afr[0][2], afr[0][3], aBase[bi] + a_off[0] * 2 + kadd);
            LDSM4(afr[1][0], afr[1][1], afr[1][2], afr[1][3], aBase[bi] + a_off[1] * 2 + kadd);
#pragma unroll
            for (int p = 0; p < 4; p++) {
                uint32_t b0, b1, b2, b3;
                LDSM4(b0, b1, b2, b3, bBase[bi] + b_off[p] * 2 + kadd);
                mma_fp16_16x8x16(acc[0][2 * p], afr[0], b0, b1);
                mma_fp16_16x8x16(acc[1][2 * p], afr[1], b0, b1);
                mma_fp16_16x8x16(acc[0][2 * p + 1], afr[0], b2, b3);
                mma_fp16_16x8x16(acc[1][2 * p + 1], afr[1], b2, b3);
            }
        }
    }
    // epilogue
    const int gr = lane >> 2;
    const int c2 = (lane & 3) * 2;
#pragma unroll
    for (int mt = 0; mt < 2; mt++) {
        int oc0 = oc_base + (wm * 2 + mt) * 16 + gr;
        float b0 = bias[oc0], b1 = bias[oc0 + 8];
        float* op0 = out + ((size_t)b * 512 + oc0) * 900;
        float* op1 = out + ((size_t)b * 512 + oc0 + 8) * 900;
#pragma unroll
        for (int nt = 0; nt < 8; nt++) {
            int sp = sp_base + (wn * 8 + nt) * 8 + c2;
            if (sp < 900) {
                *(float2*)&op0[sp] = make_float2(acc[mt][nt][0] + b0, acc[mt][nt][1] + b0);
                *(float2*)&op1[sp] = make_float2(acc[mt][nt][2] + b1, acc[mt][nt][3] + b1);
            }
        }
    }
}

// ---------------- pc2: grouped 32g, 16->8, 3x3, pad 1 (3 row slices) ----------------
__global__ void pc2_kernel(const float* __restrict__ in,
                           const float* __restrict__ w,
                           const float* __restrict__ bias,
                           float* __restrict__ out) {
    int g = blockIdx.x, b = blockIdx.y, sl = blockIdx.z;
    int oh0 = sl * 10;
    __shared__ float wsh[1152];
    __shared__ float xin[16 * 12 * 30];
    for (int idx = threadIdx.x; idx < 1152; idx += 256) wsh[idx] = w[g * 1152 + idx];
    const float* inb = in + ((size_t)b * 512 + g * 16) * 900;
    for (int idx = threadIdx.x; idx < 5760; idx += 256) {
        int iw = idx % 30;
        int r2 = idx / 30;
        int ihl = r2 % 12, i = r2 / 12;
        int ih = oh0 - 1 + ihl;
        xin[idx] = (ih >= 0 && ih < 30) ? inb[i * 900 + ih * 30 + iw] : 0.f;
    }
    __syncthreads();
    for (int spl = threadIdx.x; spl < 300; spl += 256) {
        int ohl = spl / 30, ow = spl - ohl * 30;
        int oh = oh0 + ohl;
        float acc[8];
#pragma unroll
        for (int o = 0; o < 8; o++) acc[o] = bias[g * 8 + o];
        for (int i = 0; i < 16; i++) {
            const float* ip = xin + i * 360;
#pragma unroll
            for (int kh = 0; kh < 3; kh++) {
#pragma unroll
                for (int kw = 0; kw < 3; kw++) {
                    int iw = ow - 1 + kw;
                    if (iw < 0 || iw >= 30) continue;
                    float v = ip[(ohl + kh) * 30 + iw];
                    int e = kh * 3 + kw;
#pragma unroll
                    for (int o = 0; o < 8; o++) acc[o] += v * wsh[(o * 16 + i) * 9 + e];
                }
            }
        }
#pragma unroll
        for (int o = 0; o < 8; o++)
            out[((size_t)b * 256 + g * 8 + o) * 900 + oh * 30 + ow] = acc[o];
    }
}

// ---------------- pc3: grouped 32g, 8->8, 3x3, pad 0 (30->28), 4 row slices ----------------
__global__ void pc3_kernel(const float* __restrict__ in,
                           const float* __restrict__ w,
                           const float* __restrict__ bias,
                           float* __restrict__ out) {
    int g = blockIdx.x, b = blockIdx.y, sl = blockIdx.z;
    int oh0 = sl * 7;
    __shared__ float wsh[576];
    __shared__ float xin[8 * 9 * 30];
    for (int idx = threadIdx.x; idx < 576; idx += 256) wsh[idx] = w[g * 576 + idx];
    const float* inb = in + ((size_t)b * 256 + g * 8) * 900;
    for (int idx = threadIdx.x; idx < 2160; idx += 256) {
        int iw = idx % 30;
        int r2 = idx / 30;
        int ihl = r2 % 9, i = r2 / 9;
        xin[idx] = inb[i * 900 + (oh0 + ihl) * 30 + iw];
    }
    __syncthreads();
    for (int spl = threadIdx.x; spl < 196; spl += 256) {
        int ohl = spl / 28, ow = spl - ohl * 28;
        int oh = oh0 + ohl;
        float acc[8];
#pragma unroll
        for (int o = 0; o < 8; o++) acc[o] = bias[g * 8 + o];
        for (int i = 0; i < 8; i++) {
            const float* ip = xin + i * 270;
#pragma unroll
            for (int kh = 0; kh < 3; kh++) {
#pragma unroll
                for (int kw = 0; kw < 3; kw++) {
                    float v = ip[(ohl + kh) * 30 + ow + kw];
                    int e = kh * 3 + kw;
#pragma unroll
                    for (int o = 0; o < 8; o++) acc[o] += v * wsh[(o * 8 + i) * 9 + e];
                }
            }
        }
#pragma unroll
        for (int o = 0; o < 8; o++)
            out[((size_t)b * 256 + g * 8 + o) * 784 + oh * 28 + ow] = acc[o];
    }
}

// ---------------- build u (capsule transpose) + squash over dim 8 ----------------
__global__ void u_build_kernel(const float* __restrict__ y, float* __restrict__ u) {
    int b = blockIdx.y;
    int s0 = blockIdx.x * 16;
    __shared__ float ys[256 * 16];
    for (int i = threadIdx.x; i < 4096; i += 256) {
        int ch = i >> 4, si = i & 15;
        ys[i] = y[(b * 256 + ch) * 784 + s0 + si];
    }
    __syncthreads();
    for (int p = threadIdx.x; p < 512; p += 256) {
        int si = p >> 5, cap = p & 31;
        float d[8];
        float sq = 0.f;
#pragma unroll
        for (int i = 0; i < 8; i++) {
            d[i] = ys[(cap * 8 + i) * 16 + si];
            sq += d[i] * d[i];
        }
        float f = sq / (sqrtf(sq) * (1.f + sq));
        int n = (s0 + si) * 32 + cap;
        float* up = u + ((size_t)b * 25088 + n) * 8;
#pragma unroll
        for (int i = 0; i < 8; i++) up[i] = f * d[i];
    }
}

// ---------------- fused routing pass ----------------
__global__ void routing_kernel(const float* __restrict__ W, int mode) {
    int warp = (blockIdx.x * 256 + threadIdx.x) >> 5;
    int lane = threadIdx.x & 31;
    int bhalf = lane >> 4;
    int j = lane & 15;
    float s_acc[4][10];
#pragma unroll
    for (int bp = 0; bp < 4; bp++)
#pragma unroll
        for (int k = 0; k < 10; k++) s_acc[bp][k] = 0.f;

    int n0 = warp * 8;
    for (int nn = 0; nn < 8; nn++) {
        int n = n0 + nn;
        const float* Wn = W + (size_t)n * 1280;
#pragma unroll
        for (int bp = 0; bp < 4; bp++) {
            int b = bp * 2 + bhalf;
            const float* up = g_u + ((size_t)b * 25088 + n) * 8;
            float uu[8];
#pragma unroll
            for (int i = 0; i < 8; i++) uu[i] = up[i];
            float uh[10];
#pragma unroll
            for (int k = 0; k < 10; k++) {
                float a = 0.f;
#pragma unroll
                for (int i = 0; i < 8; i++) a += uu[i] * Wn[k * 128 + i * 16 + j];
                uh[k] = a;
            }
            float c[10];
            if (mode == 0) {
#pragma unroll
                for (int k = 0; k < 10; k++) c[k] = 0.1f;
            } else {
                float bl[10];
#pragma unroll
                for (int k = 0; k < 10; k++) {
                    float d = uh[k] * g_v[(b * 10 + k) * 16 + j];
                    d += __shfl_xor_sync(0xffffffffu, d, 1);
                    d += __shfl_xor_sync(0xffffffffu, d, 2);
                    d += __shfl_xor_sync(0xffffffffu, d, 4);
                    d += __shfl_xor_sync(0xffffffffu, d, 8);
                    bl[k] = d;
                }
                if (mode == 2) {
#pragma unroll
                    for (int k = 0; k < 10; k++)
                        bl[k] += g_blog[((size_t)b * 25088 + n) * 10 + k];
                } else if (j == 0) {
#pragma unroll
                    for (int k = 0; k < 10; k++)
                        g_blog[((size_t)b * 25088 + n) * 10 + k] = bl[k];
                }
                float m = bl[0];
#pragma unroll
                for (int k = 1; k < 10; k++) m = fmaxf(m, bl[k]);
                float sum = 0.f;
#pragma unroll
                for (int k = 0; k < 10; k++) { c[k] = expf(bl[k] - m); sum += c[k]; }
                float inv = 1.f / sum;
#pragma unroll
                for (int k = 0; k < 10; k++) c[k] *= inv;
            }
#pragma unroll
            for (int k = 0; k < 10; k++) s_acc[bp][k] += c[k] * uh[k];
        }
    }
    __shared__ float ssm[8][1280];
    int wl = (threadIdx.x >> 5);
#pragma unroll
    for (int bp = 0; bp < 4; bp++) {
        int b = bp * 2 + bhalf;
#pragma unroll
        for (int k = 0; k < 10; k++)
            ssm[wl][(b * 10 + k) * 16 + j] = s_acc[bp][k];
    }
    __syncthreads();
    for (int i = threadIdx.x; i < 1280; i += 256) {
        float t = 0.f;
#pragma unroll
        for (int w = 0; w < 8; w++) t += ssm[w][i];
        g_spart[blockIdx.x * 1280 + i] = t;
    }
}

// ---------------- fused reduce + squash ----------------
__global__ void reduce_squash_kernel(float* out_opt) {
    int half = threadIdx.x >> 7;
    int t = threadIdx.x & 127;
    int i = blockIdx.x * 128 + t;  // 10 blocks x 128 = 1280
    float s = 0.f;
    for (int p = half * 196; p < half * 196 + 196; p++) s += g_spart[p * 1280 + i];
    __shared__ float sh[128];
    if (half) sh[t] = s;
    __syncthreads();
    if (!half) {
        s += sh[t];
        float sq = s * s;
        sq += __shfl_xor_sync(0xffffffffu, sq, 1);
        sq += __shfl_xor_sync(0xffffffffu, sq, 2);
        sq += __shfl_xor_sync(0xffffffffu, sq, 4);
        sq += __shfl_xor_sync(0xffffffffu, sq, 8);
        float f = sq / (sqrtf(sq) * (1.f + sq));
        float vv = f * s;
        g_v[i] = vv;
        if (out_opt) out_opt[i] = vv;
    }
}

// ---------------- decoder ----------------
__global__ void fc1_kernel(const float* __restrict__ target,
                           const float* __restrict__ w,
                           const float* __restrict__ bias) {
    int b = blockIdx.x;
    __shared__ float vm[16];
    if (threadIdx.x < 16) {
        float a = 0.f;
        for (int k = 0; k < 10; k++) a += target[b * 10 + k] * g_v[(b * 10 + k) * 16 + threadIdx.x];
        vm[threadIdx.x] = a;
    }
    __syncthreads();
    int o = threadIdx.x;
    float acc = bias[o];
#pragma unroll
    for (int i = 0; i < 16; i++) acc += vm[i] * w[o * 16 + i];
    g_h1[b * 512 + o] = fmaxf(acc, 0.f);
}

// fc2: grid (8 oslice, 8 b), 256 thr; warp-per-output, 16 outputs/warp
__global__ void fc2_kernel(const float* __restrict__ w, const float* __restrict__ bias) {
    int osl = blockIdx.x, b = blockIdx.y;
    __shared__ float h1[512];
    for (int i = threadIdx.x; i < 512; i += 256) h1[i] = g_h1[b * 512 + i];
    __syncthreads();
    int warp = threadIdx.x >> 5, lane = threadIdx.x & 31;
    for (int k = 0; k < 16; k++) {
        int o = osl * 128 + warp * 16 + k;
        const float* wr = w + (size_t)o * 512;
        float a = 0.f;
#pragma unroll
        for (int i = lane; i < 512; i += 32) a += h1[i] * wr[i];
        a += __shfl_xor_sync(0xffffffffu, a, 16);
        a += __shfl_xor_sync(0xffffffffu, a, 8);
        a += __shfl_xor_sync(0xffffffffu, a, 4);
        a += __shfl_xor_sync(0xffffffffu, a, 2);
        a += __shfl_xor_sync(0xffffffffu, a, 1);
        if (lane == 0) g_h2[b * 1024 + o] = fmaxf(a + bias[o], 0.f);
    }
}

// fc3: grid (9 oslice, 8 b), 256 thr; warp-per-output, 18 outputs/warp
__global__ void fc3_kernel(const float* __restrict__ w, const float* __restrict__ bias) {
    int osl = blockIdx.x, b = blockIdx.y;
    __shared__ float h2[1024];
    for (int i = threadIdx.x; i < 1024; i += 256) h2[i] = g_h2[b * 1024 + i];
    __syncthreads();
    int warp = threadIdx.x >> 5, lane = threadIdx.x & 31;
    for (int k = 0; k < 18; k++) {
        int o = osl * 144 + warp * 18 + k;
        const float* wr = w + (size_t)o * 1024;
        float a = 0.f;
#pragma unroll
        for (int i = lane; i < 1024; i += 32) a += h2[i] * wr[i];
        a += __shfl_xor_sync(0xffffffffu, a, 16);
        a += __shfl_xor_sync(0xffffffffu, a, 8);
        a += __shfl_xor_sync(0xffffffffu, a, 4);
        a += __shfl_xor_sync(0xffffffffu, a, 2);
        a += __shfl_xor_sync(0xffffffffu, a, 1);
        if (lane == 0) g_rec[b * 1296 + o] = 1.f / (1.f + expf(-(a + bias[o])));
    }
}

__global__ void upsample_kernel(float* __restrict__ out) {
    int idx = blockIdx.x * 256 + threadIdx.x;
    if (idx >= 8 * 5184) return;
    int b = idx / 5184;
    int r = idx - b * 5184;
    int oy = r / 72, ox = r - oy * 72;
    float sy = (float)(oy * 35) / 71.0f;
    float sx = (float)(ox * 35) / 71.0f;
    int y0 = (int)sy, x0 = (int)sx;
    int y1 = min(y0 + 1, 35), x1 = min(x0 + 1, 35);
    float wy = sy - (float)y0, wx = sx - (float)x0;
    const float* rb = g_rec + b * 1296;
    float a00 = rb[y0 * 36 + x0], a01 = rb[y0 * 36 + x1];
    float a10 = rb[y1 * 36 + x0], a11 = rb[y1 * 36 + x1];
    float v = (1.f - wy) * ((1.f - wx) * a00 + wx * a01) +
              wy * ((1.f - wx) * a10 + wx * a11);
    out[1280 + b * 5184 + r] = v;
}

// ---------------- launch ----------------
extern "C" void kernel_launch(void* const* d_in, const int* in_sizes, int n_in,
                              void* d_out, int out_size) {
    const float* x       = (const float*)d_in[0];
    const float* target  = (const float*)d_in[1];
    const float* conv1_w = (const float*)d_in[2];
    const float* conv1_b = (const float*)d_in[3];
    const float* pc1_w   = (const float*)d_in[4];
    const float* pc1_b   = (const float*)d_in[5];
    const float* pc2_w   = (const float*)d_in[6];
    const float* pc2_b   = (const float*)d_in[7];
    const float* pc3_w   = (const float*)d_in[8];
    const float* pc3_b   = (const float*)d_in[9];
    const float* W_digit = (const float*)d_in[10];
    const float* fc1_w   = (const float*)d_in[11];
    const float* fc1_b   = (const float*)d_in[12];
    const float* fc2_w   = (const float*)d_in[13];
    const float* fc2_b   = (const float*)d_in[14];
    const float* fc3_w   = (const float*)d_in[15];
    const float* fc3_b   = (const float*)d_in[16];
    float* out = (float*)d_out;

    float *pc1p, *pc2p, *pc3p, *up;
    __half *conv1p, *wpp, *bmp;
    cudaGetSymbolAddress((void**)&conv1p, g_conv1h);
    cudaGetSymbolAddress((void**)&wpp, g_wpadh);
    cudaGetSymbolAddress((void**)&bmp, g_bmat);
    cudaGetSymbolAddress((void**)&pc1p, g_pc1);
    cudaGetSymbolAddress((void**)&pc2p, g_pc2);
    cudaGetSymbolAddress((void**)&pc3p, g_pc3);
    cudaGetSymbolAddress((void**)&up, g_u);

    conv1_kernel<<<dim3(256, 8), 256>>>(x, conv1_w, conv1_b, conv1p);
    wpad_kernel<<<16384, 256>>>(pc1_w, wpp);
    im2col_kernel<<<dim3(30, 4, 8), 256>>>(conv1p, bmp);
    pc1_mma_kernel<<<dim3(8, 4, 8), 256>>>(bmp, (const uint4*)wpp, pc1_b, pc1p);
    pc2_kernel<<<dim3(32, 8, 3), 256>>>(pc1p, pc2_w, pc2_b, pc2p);
    pc3_kernel<<<dim3(32, 8, 4), 256>>>(pc2p, pc3_w, pc3_b, pc3p);
    u_build_kernel<<<dim3(49, 8), 256>>>(pc3p, up);

    // routing
    routing_kernel<<<392, 256>>>(W_digit, 0);
    reduce_squash_kernel<<<10, 256>>>(nullptr);
    routing_kernel<<<392, 256>>>(W_digit, 1);
    reduce_squash_kernel<<<10, 256>>>(nullptr);
    routing_kernel<<<392, 256>>>(W_digit, 2);
    reduce_squash_kernel<<<10, 256>>>(out);

    // decoder
    fc1_kernel<<<8, 512>>>(target, fc1_w, fc1_b);
    fc2_kernel<<<dim3(8, 8), 256>>>(fc2_w, fc2_b);
    fc3_kernel<<<dim3(9, 8), 256>>>(fc3_w, fc3_b);
    upsample_kernel<<<162, 256>>>(out);
}

// round 12
// speedup vs baseline: 1.6693x; 1.0588x over previous
#include <cuda_runtime.h>
#include <cuda_fp16.h>
#include <math.h>
#include <stdint.h>

// ---------------- scratch (static __device__, no allocations) ----------------
__device__ __align__(16) __half g_conv1h[8 * 256 * 64 * 64]; // [b][oc][64*64] fp16
__device__ __align__(16) __half g_wpadh[512 * 6400];         // pc1 weights fp16, dense K
__device__ __align__(16) __half g_bmat[8 * 900 * 6400];      // im2col [b][sp][k] fp16 dense
__device__ float g_pc1[8 * 512 * 900];         // [b][oc][30*30]
__device__ float g_pc2[8 * 256 * 900];
__device__ float g_pc3[8 * 256 * 784];         // [b][oc][28*28]
__device__ float g_u[8 * 25088 * 8];           // squashed primary caps
__device__ float g_blog[8 * 25088 * 10];       // routing logits
__device__ float g_spart[392 * 1280];          // per-block partial s
__device__ float g_v[1280];
__device__ float g_h1[8 * 512];
__device__ float g_h2[8 * 1024];
__device__ float g_rec[8 * 1296];

__device__ __forceinline__ void mma_fp16_16x8x16(float* d, const uint32_t* a,
                                                 uint32_t b0, uint32_t b1) {
    asm volatile(
        "mma.sync.aligned.m16n8k16.row.col.f32.f16.f16.f32 "
        "{%0,%1,%2,%3}, {%4,%5,%6,%7}, {%8,%9}, {%0,%1,%2,%3};"
        : "+f"(d[0]), "+f"(d[1]), "+f"(d[2]), "+f"(d[3])
        : "r"(a[0]), "r"(a[1]), "r"(a[2]), "r"(a[3]), "r"(b0), "r"(b1));
}
#define LDSM4(r0, r1, r2, r3, addr)                                         \
    asm volatile("ldmatrix.sync.aligned.m8n8.x4.shared.b16 {%0,%1,%2,%3}, [%4];" \
                 : "=r"(r0), "=r"(r1), "=r"(r2), "=r"(r3) : "r"(addr))

// ---------------- conv1: 1->256ch, 9x9, relu, fp16 out (register-tiled) ----------------
__global__ void conv1_kernel(const float* __restrict__ x,
                             const float* __restrict__ w,
                             const float* __restrict__ bias,
                             __half* __restrict__ out) {
    int oc = blockIdx.x, b = blockIdx.y;
    __shared__ float xs[72 * 72];
    __shared__ float wsh[81];
    for (int i = threadIdx.x; i < 5184; i += 256) xs[i] = x[b * 5184 + i];
    if (threadIdx.x < 81) wsh[threadIdx.x] = w[oc * 81 + threadIdx.x];
    __syncthreads();
    float bv = bias[oc];
    int og = threadIdx.x & 7;
    int r0 = threadIdx.x >> 3;
    __half* ob = out + ((size_t)(b * 256 + oc)) * 4096;
    for (int hf = 0; hf < 2; hf++) {
        int oh = r0 + hf * 32;
        int ow0 = og * 8;
        float acc[8];
#pragma unroll
        for (int o = 0; o < 8; o++) acc[o] = bv;
#pragma unroll
        for (int kh = 0; kh < 9; kh++) {
            const float* row = &xs[(oh + kh) * 72 + ow0];
            float seg[16];
#pragma unroll
            for (int s = 0; s < 16; s += 4) {
                float4 v = *(const float4*)&row[s];
                seg[s] = v.x; seg[s + 1] = v.y; seg[s + 2] = v.z; seg[s + 3] = v.w;
            }
#pragma unroll
            for (int kw = 0; kw < 9; kw++) {
                float wv = wsh[kh * 9 + kw];
#pragma unroll
                for (int o = 0; o < 8; o++) acc[o] += seg[kw + o] * wv;
            }
        }
#pragma unroll
        for (int o = 0; o < 8; o++)
            ob[oh * 64 + ow0 + o] = __float2half(fmaxf(acc[o], 0.f));
    }
}

// ---------------- pc1 weight prep: dense fp16 copy [512][6400] ----------------
__global__ void wpad_kernel(const float* __restrict__ w, __half* __restrict__ wp) {
    int idx = blockIdx.x * 256 + threadIdx.x;
    if (idx < 512 * 6400) wp[idx] = __float2half(w[idx]);
}

// ---------------- im2col dense: conv1h -> Bmat[b][sp][k], k = ic*25+e ----------------
__global__ void im2col_kernel(const __half* __restrict__ ch, __half* __restrict__ bm) {
    int oh = blockIdx.x, icc = blockIdx.y, b = blockIdx.z;
    __shared__ __half sx[64 * 324];
    const __half* src = ch + ((size_t)(b * 256 + icc * 64)) * 4096 + (2 * oh) * 64;
    for (int idx = threadIdx.x; idx < 5120; idx += 256) {
        int c4 = idx & 15;
        int r = (idx >> 4) % 5;
        int ic = idx / 80;
        *(uint2*)&sx[ic * 324 + r * 64 + c4 * 4] =
            *(const uint2*)&src[(size_t)ic * 4096 + r * 64 + c4 * 4];
    }
    __syncthreads();
    // block's k-range: [icc*1600, icc*1600+1600) -> 50 chunks of 32
    __half* dstb = bm + ((size_t)b * 900 + oh * 30) * 6400 + icc * 1600;
    for (int idx = threadIdx.x; idx < 1500; idx += 256) {
        int ow = idx % 30;
        int kc = idx / 30;       // 0..49
        int kl = kc * 32;        // local k base within block's 1600
        int ic = kl / 25;        // local ic 0..63
        int e = kl - ic * 25;
        __half hv[32];
#pragma unroll
        for (int kk = 0; kk < 32; kk++) {
            hv[kk] = sx[ic * 324 + (e / 5) * 64 + 2 * ow + (e % 5)];
            if (++e == 25) { e = 0; ic++; }
        }
        uint32_t pk[16];
#pragma unroll
        for (int t = 0; t < 16; t++) {
            __half2 p = __halves2half2(hv[2 * t], hv[2 * t + 1]);
            pk[t] = *(uint32_t*)&p;
        }
        uint4* dst = (uint4*)(dstb + (size_t)ow * 6400 + kl);
        dst[0] = make_uint4(pk[0], pk[1], pk[2], pk[3]);
        dst[1] = make_uint4(pk[4], pk[5], pk[6], pk[7]);
        dst[2] = make_uint4(pk[8], pk[9], pk[10], pk[11]);
        dst[3] = make_uint4(pk[12], pk[13], pk[14], pk[15]);
    }
}

// ---------------- pc1 via mma.sync fp16 m16n8k16, dense K=6400 (200 chunks) ----------------
#define ASTR 40   // halves per row (80B) -> conflict-free ldmatrix rows
#define KCH 200   // K chunks of 32
#define RSTR 800  // row stride in uint4 (6400 halves)
__global__ void __launch_bounds__(256, 2)
pc1_mma_kernel(const __half* __restrict__ bmat, const uint4* __restrict__ wph4,
               const float* __restrict__ bias, float* __restrict__ out) {
    __shared__ __align__(16) __half As[2][128 * ASTR];
    __shared__ __align__(16) __half Bs[2][128 * ASTR];
    const int tid = threadIdx.x;
    const int lane = tid & 31, wid = tid >> 5;
    const int spt = blockIdx.x, oct = blockIdx.y, b = blockIdx.z;
    const int oc_base = oct * 128, sp_base = spt * 128;
    const int wm = wid & 3, wn = wid >> 2;

    // producer geometry: thread covers rows rr2, rr2+64 at 16B group grp4
    const int grp4 = tid & 3;
    const int rr2 = tid >> 2;  // 0..63
    const uint4* bb[2];
    int bval[2];
#pragma unroll
    for (int q = 0; q < 2; q++) {
        int sp = sp_base + rr2 + 64 * q;
        bval[q] = (sp < 900);
        bb[q] = (const uint4*)(bmat + ((size_t)b * 900 + (bval[q] ? sp : 0)) * 6400) + grp4;
    }
    const uint4* wbase = wph4 + (size_t)oc_base * RSTR + grp4;

    float acc[2][8][4];
#pragma unroll
    for (int mt = 0; mt < 2; mt++)
#pragma unroll
        for (int nt = 0; nt < 8; nt++)
#pragma unroll
            for (int i = 0; i < 4; i++) acc[mt][nt][i] = 0.f;

    // ldmatrix per-lane address offsets (in halves)
    const int l15 = lane & 15;
    uint32_t a_off[2];
#pragma unroll
    for (int mt = 0; mt < 2; mt++)
        a_off[mt] = (uint32_t)(((wm * 2 + mt) * 16 + l15) * ASTR + ((lane >> 4) & 1) * 8);
    uint32_t b_off[4];
#pragma unroll
    for (int p = 0; p < 4; p++)
        b_off[p] = (uint32_t)((((wn * 8 + 2 * p + ((lane >> 4) & 1)) * 8) + (lane & 7)) * ASTR +
                              ((lane >> 3) & 1) * 8);
    uint32_t aBase[2], bBase[2];
#pragma unroll
    for (int bi = 0; bi < 2; bi++) {
        aBase[bi] = (uint32_t)__cvta_generic_to_shared(&As[bi][0]);
        bBase[bi] = (uint32_t)__cvta_generic_to_shared(&Bs[bi][0]);
    }

    uint4 aR[2], bR[2];
    const uint4 z4 = make_uint4(0u, 0u, 0u, 0u);
#pragma unroll
    for (int q = 0; q < 2; q++)
        aR[q] = wbase[(size_t)(rr2 + 64 * q) * RSTR];
#pragma unroll
    for (int q = 0; q < 2; q++)
        bR[q] = bval[q] ? bb[q][0] : z4;

    for (int ic = 0; ic < KCH; ic++) {
        const int bi = ic & 1;
#pragma unroll
        for (int q = 0; q < 2; q++)
            *(uint4*)&As[bi][(rr2 + 64 * q) * ASTR + grp4 * 8] = aR[q];
#pragma unroll
        for (int q = 0; q < 2; q++)
            *(uint4*)&Bs[bi][(rr2 + 64 * q) * ASTR + grp4 * 8] = bR[q];
        if (ic + 1 < KCH) {
#pragma unroll
            for (int q = 0; q < 2; q++)
                aR[q] = wbase[(size_t)(rr2 + 64 * q) * RSTR + (ic + 1) * 4];
#pragma unroll
            for (int q = 0; q < 2; q++)
                bR[q] = bval[q] ? bb[q][(ic + 1) * 4] : z4;
        }
        __syncthreads();
#pragma unroll
        for (int k16 = 0; k16 < 2; k16++) {
            const uint32_t kadd = k16 * 32;  // bytes (16 halves)
            uint32_t afr[2][4];
            LDSM4(afr[0][0], afr[0][1], afr[0][2], afr[0][3], aBase[bi] + a_off[0] * 2 + kadd);
            LDSM4(afr[1][0], afr[1][1], afr[1][2], afr[1][3], aBase[bi] + a_off[1] * 2 + kadd);
#pragma unroll
            for (int p = 0; p < 4; p++) {
                uint32_t b0, b1, b2, b3;
                LDSM4(b0, b1, b2, b3, bBase[bi] + b_off[p] * 2 + kadd);
                mma_fp16_16x8x16(acc[0][2 * p], afr[0], b0, b1);
                mma_fp16_16x8x16(acc[1][2 * p], afr[1], b0, b1);
                mma_fp16_16x8x16(acc[0][2 * p + 1], afr[0], b2, b3);
                mma_fp16_16x8x16(acc[1][2 * p + 1], afr[1], b2, b3);
            }
        }
    }
    // epilogue
    const int gr = lane >> 2;
    const int c2 = (lane & 3) * 2;
#pragma unroll
    for (int mt = 0; mt < 2; mt++) {
        int oc0 = oc_base + (wm * 2 + mt) * 16 + gr;
        float b0 = bias[oc0], b1 = bias[oc0 + 8];
        float* op0 = out + ((size_t)b * 512 + oc0) * 900;
        float* op1 = out + ((size_t)b * 512 + oc0 + 8) * 900;
#pragma unroll
        for (int nt = 0; nt < 8; nt++) {
            int sp = sp_base + (wn * 8 + nt) * 8 + c2;
            if (sp < 900) {
                *(float2*)&op0[sp] = make_float2(acc[mt][nt][0] + b0, acc[mt][nt][1] + b0);
                *(float2*)&op1[sp] = make_float2(acc[mt][nt][2] + b1, acc[mt][nt][3] + b1);
            }
        }
    }
}

// ---------------- pc2: grouped 32g, 16->8, 3x3, pad 1 (3 row slices) ----------------
__global__ void pc2_kernel(const float* __restrict__ in,
                           const float* __restrict__ w,
                           const float* __restrict__ bias,
                           float* __restrict__ out) {
    int g = blockIdx.x, b = blockIdx.y, sl = blockIdx.z;
    int oh0 = sl * 10;
    __shared__ float wsh[1152];
    __shared__ float xin[16 * 12 * 30];
    for (int idx = threadIdx.x; idx < 1152; idx += 256) wsh[idx] = w[g * 1152 + idx];
    const float* inb = in + ((size_t)b * 512 + g * 16) * 900;
    for (int idx = threadIdx.x; idx < 5760; idx += 256) {
        int iw = idx % 30;
        int r2 = idx / 30;
        int ihl = r2 % 12, i = r2 / 12;
        int ih = oh0 - 1 + ihl;
        xin[idx] = (ih >= 0 && ih < 30) ? inb[i * 900 + ih * 30 + iw] : 0.f;
    }
    __syncthreads();
    for (int spl = threadIdx.x; spl < 300; spl += 256) {
        int ohl = spl / 30, ow = spl - ohl * 30;
        int oh = oh0 + ohl;
        float acc[8];
#pragma unroll
        for (int o = 0; o < 8; o++) acc[o] = bias[g * 8 + o];
        for (int i = 0; i < 16; i++) {
            const float* ip = xin + i * 360;
#pragma unroll
            for (int kh = 0; kh < 3; kh++) {
#pragma unroll
                for (int kw = 0; kw < 3; kw++) {
                    int iw = ow - 1 + kw;
                    if (iw < 0 || iw >= 30) continue;
                    float v = ip[(ohl + kh) * 30 + iw];
                    int e = kh * 3 + kw;
#pragma unroll
                    for (int o = 0; o < 8; o++) acc[o] += v * wsh[(o * 16 + i) * 9 + e];
                }
            }
        }
#pragma unroll
        for (int o = 0; o < 8; o++)
            out[((size_t)b * 256 + g * 8 + o) * 900 + oh * 30 + ow] = acc[o];
    }
}

// ---------------- pc3: grouped 32g, 8->8, 3x3, pad 0 (30->28), 4 row slices ----------------
__global__ void pc3_kernel(const float* __restrict__ in,
                           const float* __restrict__ w,
                           const float* __restrict__ bias,
                           float* __restrict__ out) {
    int g = blockIdx.x, b = blockIdx.y, sl = blockIdx.z;
    int oh0 = sl * 7;
    __shared__ float wsh[576];
    __shared__ float xin[8 * 9 * 30];
    for (int idx = threadIdx.x; idx < 576; idx += 256) wsh[idx] = w[g * 576 + idx];
    const float* inb = in + ((size_t)b * 256 + g * 8) * 900;
    for (int idx = threadIdx.x; idx < 2160; idx += 256) {
        int iw = idx % 30;
        int r2 = idx / 30;
        int ihl = r2 % 9, i = r2 / 9;
        xin[idx] = inb[i * 900 + (oh0 + ihl) * 30 + iw];
    }
    __syncthreads();
    for (int spl = threadIdx.x; spl < 196; spl += 256) {
        int ohl = spl / 28, ow = spl - ohl * 28;
        int oh = oh0 + ohl;
        float acc[8];
#pragma unroll
        for (int o = 0; o < 8; o++) acc[o] = bias[g * 8 + o];
        for (int i = 0; i < 8; i++) {
            const float* ip = xin + i * 270;
#pragma unroll
            for (int kh = 0; kh < 3; kh++) {
#pragma unroll
                for (int kw = 0; kw < 3; kw++) {
                    float v = ip[(ohl + kh) * 30 + ow + kw];
                    int e = kh * 3 + kw;
#pragma unroll
                    for (int o = 0; o < 8; o++) acc[o] += v * wsh[(o * 8 + i) * 9 + e];
                }
            }
        }
#pragma unroll
        for (int o = 0; o < 8; o++)
            out[((size_t)b * 256 + g * 8 + o) * 784 + oh * 28 + ow] = acc[o];
    }
}

// ---------------- build u (capsule transpose) + squash over dim 8 ----------------
__global__ void u_build_kernel(const float* __restrict__ y, float* __restrict__ u) {
    int b = blockIdx.y;
    int s0 = blockIdx.x * 16;
    __shared__ float ys[256 * 16];
    for (int i = threadIdx.x; i < 4096; i += 256) {
        int ch = i >> 4, si = i & 15;
        ys[i] = y[(b * 256 + ch) * 784 + s0 + si];
    }
    __syncthreads();
    for (int p = threadIdx.x; p < 512; p += 256) {
        int si = p >> 5, cap = p & 31;
        float d[8];
        float sq = 0.f;
#pragma unroll
        for (int i = 0; i < 8; i++) {
            d[i] = ys[(cap * 8 + i) * 16 + si];
            sq += d[i] * d[i];
        }
        float f = sq / (sqrtf(sq) * (1.f + sq));
        int n = (s0 + si) * 32 + cap;
        float* up = u + ((size_t)b * 25088 + n) * 8;
#pragma unroll
        for (int i = 0; i < 8; i++) up[i] = f * d[i];
    }
}

// ---------------- fused routing pass ----------------
__global__ void routing_kernel(const float* __restrict__ W, int mode) {
    int warp = (blockIdx.x * 256 + threadIdx.x) >> 5;
    int lane = threadIdx.x & 31;
    int bhalf = lane >> 4;
    int j = lane & 15;
    float s_acc[4][10];
#pragma unroll
    for (int bp = 0; bp < 4; bp++)
#pragma unroll
        for (int k = 0; k < 10; k++) s_acc[bp][k] = 0.f;

    int n0 = warp * 8;
    for (int nn = 0; nn < 8; nn++) {
        int n = n0 + nn;
        const float* Wn = W + (size_t)n * 1280;
#pragma unroll
        for (int bp = 0; bp < 4; bp++) {
            int b = bp * 2 + bhalf;
            const float* up = g_u + ((size_t)b * 25088 + n) * 8;
            float uu[8];
#pragma unroll
            for (int i = 0; i < 8; i++) uu[i] = up[i];
            float uh[10];
#pragma unroll
            for (int k = 0; k < 10; k++) {
                float a = 0.f;
#pragma unroll
                for (int i = 0; i < 8; i++) a += uu[i] * Wn[k * 128 + i * 16 + j];
                uh[k] = a;
            }
            float c[10];
            if (mode == 0) {
#pragma unroll
                for (int k = 0; k < 10; k++) c[k] = 0.1f;
            } else {
                float bl[10];
#pragma unroll
                for (int k = 0; k < 10; k++) {
                    float d = uh[k] * g_v[(b * 10 + k) * 16 + j];
                    d += __shfl_xor_sync(0xffffffffu, d, 1);
                    d += __shfl_xor_sync(0xffffffffu, d, 2);
                    d += __shfl_xor_sync(0xffffffffu, d, 4);
                    d += __shfl_xor_sync(0xffffffffu, d, 8);
                    bl[k] = d;
                }
                if (mode == 2) {
#pragma unroll
                    for (int k = 0; k < 10; k++)
                        bl[k] += g_blog[((size_t)b * 25088 + n) * 10 + k];
                } else if (j == 0) {
#pragma unroll
                    for (int k = 0; k < 10; k++)
                        g_blog[((size_t)b * 25088 + n) * 10 + k] = bl[k];
                }
                float m = bl[0];
#pragma unroll
                for (int k = 1; k < 10; k++) m = fmaxf(m, bl[k]);
                float sum = 0.f;
#pragma unroll
                for (int k = 0; k < 10; k++) { c[k] = __expf(bl[k] - m); sum += c[k]; }
                float inv = 1.f / sum;
#pragma unroll
                for (int k = 0; k < 10; k++) c[k] *= inv;
            }
#pragma unroll
            for (int k = 0; k < 10; k++) s_acc[bp][k] += c[k] * uh[k];
        }
    }
    __shared__ float ssm[8][1280];
    int wl = (threadIdx.x >> 5);
#pragma unroll
    for (int bp = 0; bp < 4; bp++) {
        int b = bp * 2 + bhalf;
#pragma unroll
        for (int k = 0; k < 10; k++)
            ssm[wl][(b * 10 + k) * 16 + j] = s_acc[bp][k];
    }
    __syncthreads();
    for (int i = threadIdx.x; i < 1280; i += 256) {
        float t = 0.f;
#pragma unroll
        for (int w = 0; w < 8; w++) t += ssm[w][i];
        g_spart[blockIdx.x * 1280 + i] = t;
    }
}

// ---------------- fused reduce + squash ----------------
__global__ void reduce_squash_kernel(float* out_opt) {
    int half = threadIdx.x >> 7;
    int t = threadIdx.x & 127;
    int i = blockIdx.x * 128 + t;  // 10 blocks x 128 = 1280
    float s = 0.f;
    for (int p = half * 196; p < half * 196 + 196; p++) s += g_spart[p * 1280 + i];
    __shared__ float sh[128];
    if (half) sh[t] = s;
    __syncthreads();
    if (!half) {
        s += sh[t];
        float sq = s * s;
        sq += __shfl_xor_sync(0xffffffffu, sq, 1);
        sq += __shfl_xor_sync(0xffffffffu, sq, 2);
        sq += __shfl_xor_sync(0xffffffffu, sq, 4);
        sq += __shfl_xor_sync(0xffffffffu, sq, 8);
        float f = sq / (sqrtf(sq) * (1.f + sq));
        float vv = f * s;
        g_v[i] = vv;
        if (out_opt) out_opt[i] = vv;
    }
}

// ---------------- decoder ----------------
__global__ void fc1_kernel(const float* __restrict__ target,
                           const float* __restrict__ w,
                           const float* __restrict__ bias) {
    int b = blockIdx.x;
    __shared__ float vm[16];
    if (threadIdx.x < 16) {
        float a = 0.f;
        for (int k = 0; k < 10; k++) a += target[b * 10 + k] * g_v[(b * 10 + k) * 16 + threadIdx.x];
        vm[threadIdx.x] = a;
    }
    __syncthreads();
    int o = threadIdx.x;
    float acc = bias[o];
#pragma unroll
    for (int i = 0; i < 16; i++) acc += vm[i] * w[o * 16 + i];
    g_h1[b * 512 + o] = fmaxf(acc, 0.f);
}

// fc2: grid (8 oslice, 8 b), 256 thr; warp-per-output, 16 outputs/warp
__global__ void fc2_kernel(const float* __restrict__ w, const float* __restrict__ bias) {
    int osl = blockIdx.x, b = blockIdx.y;
    __shared__ float h1[512];
    for (int i = threadIdx.x; i < 512; i += 256) h1[i] = g_h1[b * 512 + i];
    __syncthreads();
    int warp = threadIdx.x >> 5, lane = threadIdx.x & 31;
    for (int k = 0; k < 16; k++) {
        int o = osl * 128 + warp * 16 + k;
        const float* wr = w + (size_t)o * 512;
        float a = 0.f;
#pragma unroll
        for (int i = lane; i < 512; i += 32) a += h1[i] * wr[i];
        a += __shfl_xor_sync(0xffffffffu, a, 16);
        a += __shfl_xor_sync(0xffffffffu, a, 8);
        a += __shfl_xor_sync(0xffffffffu, a, 4);
        a += __shfl_xor_sync(0xffffffffu, a, 2);
        a += __shfl_xor_sync(0xffffffffu, a, 1);
        if (lane == 0) g_h2[b * 1024 + o] = fmaxf(a + bias[o], 0.f);
    }
}

// fc3: grid (9 oslice, 8 b), 256 thr; warp-per-output, 18 outputs/warp
__global__ void fc3_kernel(const float* __restrict__ w, const float* __restrict__ bias) {
    int osl = blockIdx.x, b = blockIdx.y;
    __shared__ float h2[1024];
    for (int i = threadIdx.x; i < 1024; i += 256) h2[i] = g_h2[b * 1024 + i];
    __syncthreads();
    int warp = threadIdx.x >> 5, lane = threadIdx.x & 31;
    for (int k = 0; k < 18; k++) {
        int o = osl * 144 + warp * 18 + k;
        const float* wr = w + (size_t)o * 1024;
        float a = 0.f;
#pragma unroll
        for (int i = lane; i < 1024; i += 32) a += h2[i] * wr[i];
        a += __shfl_xor_sync(0xffffffffu, a, 16);
        a += __shfl_xor_sync(0xffffffffu, a, 8);
        a += __shfl_xor_sync(0xffffffffu, a, 4);
        a += __shfl_xor_sync(0xffffffffu, a, 2);
        a += __shfl_xor_sync(0xffffffffu, a, 1);
        if (lane == 0) g_rec[b * 1296 + o] = 1.f / (1.f + __expf(-(a + bias[o])));
    }
}

__global__ void upsample_kernel(float* __restrict__ out) {
    int idx = blockIdx.x * 256 + threadIdx.x;
    if (idx >= 8 * 5184) return;
    int b = idx / 5184;
    int r = idx - b * 5184;
    int oy = r / 72, ox = r - oy * 72;
    float sy = (float)(oy * 35) / 71.0f;
    float sx = (float)(ox * 35) / 71.0f;
    int y0 = (int)sy, x0 = (int)sx;
    int y1 = min(y0 + 1, 35), x1 = min(x0 + 1, 35);
    float wy = sy - (float)y0, wx = sx - (float)x0;
    const float* rb = g_rec + b * 1296;
    float a00 = rb[y0 * 36 + x0], a01 = rb[y0 * 36 + x1];
    float a10 = rb[y1 * 36 + x0], a11 = rb[y1 * 36 + x1];
    float v = (1.f - wy) * ((1.f - wx) * a00 + wx * a01) +
              wy * ((1.f - wx) * a10 + wx * a11);
    out[1280 + b * 5184 + r] = v;
}

// ---------------- launch ----------------
extern "C" void kernel_launch(void* const* d_in, const int* in_sizes, int n_in,
                              void* d_out, int out_size) {
    const float* x       = (const float*)d_in[0];
    const float* target  = (const float*)d_in[1];
    const float* conv1_w = (const float*)d_in[2];
    const float* conv1_b = (const float*)d_in[3];
    const float* pc1_w   = (const float*)d_in[4];
    const float* pc1_b   = (const float*)d_in[5];
    const float* pc2_w   = (const float*)d_in[6];
    const float* pc2_b   = (const float*)d_in[7];
    const float* pc3_w   = (const float*)d_in[8];
    const float* pc3_b   = (const float*)d_in[9];
    const float* W_digit = (const float*)d_in[10];
    const float* fc1_w   = (const float*)d_in[11];
    const float* fc1_b   = (const float*)d_in[12];
    const float* fc2_w   = (const float*)d_in[13];
    const float* fc2_b   = (const float*)d_in[14];
    const float* fc3_w   = (const float*)d_in[15];
    const float* fc3_b   = (const float*)d_in[16];
    float* out = (float*)d_out;

    float *pc1p, *pc2p, *pc3p, *up;
    __half *conv1p, *wpp, *bmp;
    cudaGetSymbolAddress((void**)&conv1p, g_conv1h);
    cudaGetSymbolAddress((void**)&wpp, g_wpadh);
    cudaGetSymbolAddress((void**)&bmp, g_bmat);
    cudaGetSymbolAddress((void**)&pc1p, g_pc1);
    cudaGetSymbolAddress((void**)&pc2p, g_pc2);
    cudaGetSymbolAddress((void**)&pc3p, g_pc3);
    cudaGetSymbolAddress((void**)&up, g_u);

    conv1_kernel<<<dim3(256, 8), 256>>>(x, conv1_w, conv1_b, conv1p);
    wpad_kernel<<<12800, 256>>>(pc1_w, wpp);
    im2col_kernel<<<dim3(30, 4, 8), 256>>>(conv1p, bmp);
    pc1_mma_kernel<<<dim3(8, 4, 8), 256>>>(bmp, (const uint4*)wpp, pc1_b, pc1p);
    pc2_kernel<<<dim3(32, 8, 3), 256>>>(pc1p, pc2_w, pc2_b, pc2p);
    pc3_kernel<<<dim3(32, 8, 4), 256>>>(pc2p, pc3_w, pc3_b, pc3p);
    u_build_kernel<<<dim3(49, 8), 256>>>(pc3p, up);

    // routing
    routing_kernel<<<392, 256>>>(W_digit, 0);
    reduce_squash_kernel<<<10, 256>>>(nullptr);
    routing_kernel<<<392, 256>>>(W_digit, 1);
    reduce_squash_kernel<<<10, 256>>>(nullptr);
    routing_kernel<<<392, 256>>>(W_digit, 2);
    reduce_squash_kernel<<<10, 256>>>(out);

    // decoder
    fc1_kernel<<<8, 512>>>(target, fc1_w, fc1_b);
    fc2_kernel<<<dim3(8, 8), 256>>>(fc2_w, fc2_b);
    fc3_kernel<<<dim3(9, 8), 256>>>(fc3_w, fc3_b);
    upsample_kernel<<<162, 256>>>(out);
}

// round 13
// speedup vs baseline: 1.7597x; 1.0541x over previous
#include <cuda_runtime.h>
#include <cuda_fp16.h>
#include <math.h>
#include <stdint.h>

// ---------------- scratch (static __device__, no allocations) ----------------
__device__ __align__(16) __half g_conv1h[8 * 256 * 64 * 64]; // [b][oc][64*64] fp16
__device__ __align__(16) __half g_wpadh[512 * 6400];         // pc1 weights fp16, dense K
__device__ __align__(16) __half g_bmat[8 * 900 * 6400];      // im2col [b][sp][k] fp16 dense
__device__ __align__(16) __half g_uhath[(size_t)8 * 25088 * 10 * 16]; // u_hat fp16
__device__ float g_pc1[8 * 512 * 900];         // [b][oc][30*30]
__device__ float g_pc2[8 * 256 * 900];
__device__ float g_pc3[8 * 256 * 784];         // [b][oc][28*28]
__device__ float g_u[8 * 25088 * 8];           // squashed primary caps
__device__ float g_blog[8 * 25088 * 10];       // routing logits
__device__ float g_spart[392 * 1280];          // per-block partial s
__device__ float g_v[1280];
__device__ float g_h1[8 * 512];
__device__ float g_h2[8 * 1024];
__device__ float g_rec[8 * 1296];

__device__ __forceinline__ void mma_fp16_16x8x16(float* d, const uint32_t* a,
                                                 uint32_t b0, uint32_t b1) {
    asm volatile(
        "mma.sync.aligned.m16n8k16.row.col.f32.f16.f16.f32 "
        "{%0,%1,%2,%3}, {%4,%5,%6,%7}, {%8,%9}, {%0,%1,%2,%3};"
        : "+f"(d[0]), "+f"(d[1]), "+f"(d[2]), "+f"(d[3])
        : "r"(a[0]), "r"(a[1]), "r"(a[2]), "r"(a[3]), "r"(b0), "r"(b1));
}
#define LDSM4(r0, r1, r2, r3, addr)                                         \
    asm volatile("ldmatrix.sync.aligned.m8n8.x4.shared.b16 {%0,%1,%2,%3}, [%4];" \
                 : "=r"(r0), "=r"(r1), "=r"(r2), "=r"(r3) : "r"(addr))
__device__ __forceinline__ void cp_async16(uint32_t dst, const void* src, int srcsize) {
    asm volatile("cp.async.cg.shared.global [%0], [%1], 16, %2;"
                 :: "r"(dst), "l"(src), "r"(srcsize) : "memory");
}
#define CP_COMMIT() asm volatile("cp.async.commit_group;" ::: "memory")

// ---------------- conv1: 1->256ch, 9x9, relu, fp16 out (register-tiled) ----------------
__global__ void conv1_kernel(const float* __restrict__ x,
                             const float* __restrict__ w,
                             const float* __restrict__ bias,
                             __half* __restrict__ out) {
    int oc = blockIdx.x, b = blockIdx.y;
    __shared__ float xs[72 * 72];
    __shared__ float wsh[81];
    for (int i = threadIdx.x; i < 5184; i += 256) xs[i] = x[b * 5184 + i];
    if (threadIdx.x < 81) wsh[threadIdx.x] = w[oc * 81 + threadIdx.x];
    __syncthreads();
    float bv = bias[oc];
    int og = threadIdx.x & 7;
    int r0 = threadIdx.x >> 3;
    __half* ob = out + ((size_t)(b * 256 + oc)) * 4096;
    for (int hf = 0; hf < 2; hf++) {
        int oh = r0 + hf * 32;
        int ow0 = og * 8;
        float acc[8];
#pragma unroll
        for (int o = 0; o < 8; o++) acc[o] = bv;
#pragma unroll
        for (int kh = 0; kh < 9; kh++) {
            const float* row = &xs[(oh + kh) * 72 + ow0];
            float seg[16];
#pragma unroll
            for (int s = 0; s < 16; s += 4) {
                float4 v = *(const float4*)&row[s];
                seg[s] = v.x; seg[s + 1] = v.y; seg[s + 2] = v.z; seg[s + 3] = v.w;
            }
#pragma unroll
            for (int kw = 0; kw < 9; kw++) {
                float wv = wsh[kh * 9 + kw];
#pragma unroll
                for (int o = 0; o < 8; o++) acc[o] += seg[kw + o] * wv;
            }
        }
#pragma unroll
        for (int o = 0; o < 8; o++)
            ob[oh * 64 + ow0 + o] = __float2half(fmaxf(acc[o], 0.f));
    }
}

// ---------------- pc1 weight prep: dense fp16 copy [512][6400] ----------------
__global__ void wpad_kernel(const float* __restrict__ w, __half* __restrict__ wp) {
    int idx = blockIdx.x * 256 + threadIdx.x;
    if (idx < 512 * 6400) wp[idx] = __float2half(w[idx]);
}

// ---------------- im2col dense: conv1h -> Bmat[b][sp][k], k = ic*25+e ----------------
__global__ void im2col_kernel(const __half* __restrict__ ch, __half* __restrict__ bm) {
    int oh = blockIdx.x, icc = blockIdx.y, b = blockIdx.z;
    __shared__ __half sx[64 * 324];
    const __half* src = ch + ((size_t)(b * 256 + icc * 64)) * 4096 + (2 * oh) * 64;
    for (int idx = threadIdx.x; idx < 5120; idx += 256) {
        int c4 = idx & 15;
        int r = (idx >> 4) % 5;
        int ic = idx / 80;
        *(uint2*)&sx[ic * 324 + r * 64 + c4 * 4] =
            *(const uint2*)&src[(size_t)ic * 4096 + r * 64 + c4 * 4];
    }
    __syncthreads();
    __half* dstb = bm + ((size_t)b * 900 + oh * 30) * 6400 + icc * 1600;
    for (int idx = threadIdx.x; idx < 1500; idx += 256) {
        int ow = idx % 30;
        int kc = idx / 30;
        int kl = kc * 32;
        int ic = kl / 25;
        int e = kl - ic * 25;
        __half hv[32];
#pragma unroll
        for (int kk = 0; kk < 32; kk++) {
            hv[kk] = sx[ic * 324 + (e / 5) * 64 + 2 * ow + (e % 5)];
            if (++e == 25) { e = 0; ic++; }
        }
        uint32_t pk[16];
#pragma unroll
        for (int t = 0; t < 16; t++) {
            __half2 p = __halves2half2(hv[2 * t], hv[2 * t + 1]);
            pk[t] = *(uint32_t*)&p;
        }
        uint4* dst = (uint4*)(dstb + (size_t)ow * 6400 + kl);
        dst[0] = make_uint4(pk[0], pk[1], pk[2], pk[3]);
        dst[1] = make_uint4(pk[4], pk[5], pk[6], pk[7]);
        dst[2] = make_uint4(pk[8], pk[9], pk[10], pk[11]);
        dst[3] = make_uint4(pk[12], pk[13], pk[14], pk[15]);
    }
}

// ---------------- pc1 via mma.sync fp16 m16n8k16, cp.async 2-stage pipeline ----------------
#define ASTR 40   // halves per row (80B) -> conflict-free ldmatrix rows
#define KCH 200   // K chunks of 32
#define RSTR 800  // row stride in uint4 (6400 halves)
__global__ void __launch_bounds__(256, 2)
pc1_mma_kernel(const __half* __restrict__ bmat, const uint4* __restrict__ wph4,
               const float* __restrict__ bias, float* __restrict__ out) {
    __shared__ __align__(16) __half As[2][128 * ASTR];
    __shared__ __align__(16) __half Bs[2][128 * ASTR];
    const int tid = threadIdx.x;
    const int lane = tid & 31, wid = tid >> 5;
    const int spt = blockIdx.x, oct = blockIdx.y, b = blockIdx.z;
    const int oc_base = oct * 128, sp_base = spt * 128;
    const int wm = wid & 3, wn = wid >> 2;

    // producer geometry: thread covers rows rr2, rr2+64 at 16B group grp4
    const int grp4 = tid & 3;
    const int rr2 = tid >> 2;  // 0..63
    const uint4* bb[2];
    int bsz[2];
#pragma unroll
    for (int q = 0; q < 2; q++) {
        int sp = sp_base + rr2 + 64 * q;
        bsz[q] = (sp < 900) ? 16 : 0;
        bb[q] = (const uint4*)(bmat + ((size_t)b * 900 + (sp < 900 ? sp : 0)) * 6400) + grp4;
    }
    const uint4* wbase = wph4 + (size_t)oc_base * RSTR + grp4;

    // per-thread smem dst byte offsets
    uint32_t aDst[2][2], bDst[2][2];
#pragma unroll
    for (int bi = 0; bi < 2; bi++) {
        uint32_t ab = (uint32_t)__cvta_generic_to_shared(&As[bi][0]);
        uint32_t bbs = (uint32_t)__cvta_generic_to_shared(&Bs[bi][0]);
#pragma unroll
        for (int q = 0; q < 2; q++) {
            aDst[bi][q] = ab + ((rr2 + 64 * q) * ASTR + grp4 * 8) * 2;
            bDst[bi][q] = bbs + ((rr2 + 64 * q) * ASTR + grp4 * 8) * 2;
        }
    }

    float acc[2][8][4];
#pragma unroll
    for (int mt = 0; mt < 2; mt++)
#pragma unroll
        for (int nt = 0; nt < 8; nt++)
#pragma unroll
            for (int i = 0; i < 4; i++) acc[mt][nt][i] = 0.f;

    // ldmatrix per-lane address offsets (in halves)
    const int l15 = lane & 15;
    uint32_t a_off[2];
#pragma unroll
    for (int mt = 0; mt < 2; mt++)
        a_off[mt] = (uint32_t)(((wm * 2 + mt) * 16 + l15) * ASTR + ((lane >> 4) & 1) * 8);
    uint32_t b_off[4];
#pragma unroll
    for (int p = 0; p < 4; p++)
        b_off[p] = (uint32_t)((((wn * 8 + 2 * p + ((lane >> 4) & 1)) * 8) + (lane & 7)) * ASTR +
                              ((lane >> 3) & 1) * 8);
    uint32_t aBase[2], bBase[2];
#pragma unroll
    for (int bi = 0; bi < 2; bi++) {
        aBase[bi] = (uint32_t)__cvta_generic_to_shared(&As[bi][0]);
        bBase[bi] = (uint32_t)__cvta_generic_to_shared(&Bs[bi][0]);
    }

    // prologue: issue chunk 0 into buffer 0
#pragma unroll
    for (int q = 0; q < 2; q++)
        cp_async16(aDst[0][q], wbase + (size_t)(rr2 + 64 * q) * RSTR, 16);
#pragma unroll
    for (int q = 0; q < 2; q++)
        cp_async16(bDst[0][q], bb[q], bsz[q]);
    CP_COMMIT();

    for (int ic = 0; ic < KCH; ic++) {
        const int bi = ic & 1;
        if (ic + 1 < KCH) {
            const int bj = bi ^ 1;
#pragma unroll
            for (int q = 0; q < 2; q++)
                cp_async16(aDst[bj][q], wbase + (size_t)(rr2 + 64 * q) * RSTR + (ic + 1) * 4, 16);
#pragma unroll
            for (int q = 0; q < 2; q++)
                cp_async16(bDst[bj][q], bb[q] + (ic + 1) * 4, bsz[q]);
            CP_COMMIT();
            asm volatile("cp.async.wait_group 1;" ::: "memory");
        } else {
            asm volatile("cp.async.wait_group 0;" ::: "memory");
        }
        __syncthreads();
#pragma unroll
        for (int k16 = 0; k16 < 2; k16++) {
            const uint32_t kadd = k16 * 32;  // bytes (16 halves)
            uint32_t afr[2][4];
            LDSM4(afr[0][0], afr[0][1], afr[0][2], afr[0][3], aBase[bi] + a_off[0] * 2 + kadd);
            LDSM4(afr[1][0], afr[1][1], afr[1][2], afr[1][3], aBase[bi] + a_off[1] * 2 + kadd);
#pragma unroll
            for (int p = 0; p < 4; p++) {
                uint32_t b0, b1, b2, b3;
                LDSM4(b0, b1, b2, b3, bBase[bi] + b_off[p] * 2 + kadd);
                mma_fp16_16x8x16(acc[0][2 * p], afr[0], b0, b1);
                mma_fp16_16x8x16(acc[1][2 * p], afr[1], b0, b1);
                mma_fp16_16x8x16(acc[0][2 * p + 1], afr[0], b2, b3);
                mma_fp16_16x8x16(acc[1][2 * p + 1], afr[1], b2, b3);
            }
        }
        __syncthreads();  // reads of buffer bi done before it is re-targeted at ic+2
    }
    // epilogue
    const int gr = lane >> 2;
    const int c2 = (lane & 3) * 2;
#pragma unroll
    for (int mt = 0; mt < 2; mt++) {
        int oc0 = oc_base + (wm * 2 + mt) * 16 + gr;
        float b0 = bias[oc0], b1 = bias[oc0 + 8];
        float* op0 = out + ((size_t)b * 512 + oc0) * 900;
        float* op1 = out + ((size_t)b * 512 + oc0 + 8) * 900;
#pragma unroll
        for (int nt = 0; nt < 8; nt++) {
            int sp = sp_base + (wn * 8 + nt) * 8 + c2;
            if (sp < 900) {
                *(float2*)&op0[sp] = make_float2(acc[mt][nt][0] + b0, acc[mt][nt][1] + b0);
                *(float2*)&op1[sp] = make_float2(acc[mt][nt][2] + b1, acc[mt][nt][3] + b1);
            }
        }
    }
}

// ---------------- pc2: grouped 32g, 16->8, 3x3, pad 1 (3 row slices) ----------------
__global__ void pc2_kernel(const float* __restrict__ in,
                           const float* __restrict__ w,
                           const float* __restrict__ bias,
                           float* __restrict__ out) {
    int g = blockIdx.x, b = blockIdx.y, sl = blockIdx.z;
    int oh0 = sl * 10;
    __shared__ float wsh[1152];
    __shared__ float xin[16 * 12 * 30];
    for (int idx = threadIdx.x; idx < 1152; idx += 256) wsh[idx] = w[g * 1152 + idx];
    const float* inb = in + ((size_t)b * 512 + g * 16) * 900;
    for (int idx = threadIdx.x; idx < 5760; idx += 256) {
        int iw = idx % 30;
        int r2 = idx / 30;
        int ihl = r2 % 12, i = r2 / 12;
        int ih = oh0 - 1 + ihl;
        xin[idx] = (ih >= 0 && ih < 30) ? inb[i * 900 + ih * 30 + iw] : 0.f;
    }
    __syncthreads();
    for (int spl = threadIdx.x; spl < 300; spl += 256) {
        int ohl = spl / 30, ow = spl - ohl * 30;
        int oh = oh0 + ohl;
        float acc[8];
#pragma unroll
        for (int o = 0; o < 8; o++) acc[o] = bias[g * 8 + o];
        for (int i = 0; i < 16; i++) {
            const float* ip = xin + i * 360;
#pragma unroll
            for (int kh = 0; kh < 3; kh++) {
#pragma unroll
                for (int kw = 0; kw < 3; kw++) {
                    int iw = ow - 1 + kw;
                    if (iw < 0 || iw >= 30) continue;
                    float v = ip[(ohl + kh) * 30 + iw];
                    int e = kh * 3 + kw;
#pragma unroll
                    for (int o = 0; o < 8; o++) acc[o] += v * wsh[(o * 16 + i) * 9 + e];
                }
            }
        }
#pragma unroll
        for (int o = 0; o < 8; o++)
            out[((size_t)b * 256 + g * 8 + o) * 900 + oh * 30 + ow] = acc[o];
    }
}

// ---------------- pc3: grouped 32g, 8->8, 3x3, pad 0 (30->28), 4 row slices ----------------
__global__ void pc3_kernel(const float* __restrict__ in,
                           const float* __restrict__ w,
                           const float* __restrict__ bias,
                           float* __restrict__ out) {
    int g = blockIdx.x, b = blockIdx.y, sl = blockIdx.z;
    int oh0 = sl * 7;
    __shared__ float wsh[576];
    __shared__ float xin[8 * 9 * 30];
    for (int idx = threadIdx.x; idx < 576; idx += 256) wsh[idx] = w[g * 576 + idx];
    const float* inb = in + ((size_t)b * 256 + g * 8) * 900;
    for (int idx = threadIdx.x; idx < 2160; idx += 256) {
        int iw = idx % 30;
        int r2 = idx / 30;
        int ihl = r2 % 9, i = r2 / 9;
        xin[idx] = inb[i * 900 + (oh0 + ihl) * 30 + iw];
    }
    __syncthreads();
    for (int spl = threadIdx.x; spl < 196; spl += 256) {
        int ohl = spl / 28, ow = spl - ohl * 28;
        int oh = oh0 + ohl;
        float acc[8];
#pragma unroll
        for (int o = 0; o < 8; o++) acc[o] = bias[g * 8 + o];
        for (int i = 0; i < 8; i++) {
            const float* ip = xin + i * 270;
#pragma unroll
            for (int kh = 0; kh < 3; kh++) {
#pragma unroll
                for (int kw = 0; kw < 3; kw++) {
                    float v = ip[(ohl + kh) * 30 + ow + kw];
                    int e = kh * 3 + kw;
#pragma unroll
                    for (int o = 0; o < 8; o++) acc[o] += v * wsh[(o * 8 + i) * 9 + e];
                }
            }
        }
#pragma unroll
        for (int o = 0; o < 8; o++)
            out[((size_t)b * 256 + g * 8 + o) * 784 + oh * 28 + ow] = acc[o];
    }
}

// ---------------- build u (capsule transpose) + squash over dim 8 ----------------
__global__ void u_build_kernel(const float* __restrict__ y, float* __restrict__ u) {
    int b = blockIdx.y;
    int s0 = blockIdx.x * 16;
    __shared__ float ys[256 * 16];
    for (int i = threadIdx.x; i < 4096; i += 256) {
        int ch = i >> 4, si = i & 15;
        ys[i] = y[(b * 256 + ch) * 784 + s0 + si];
    }
    __syncthreads();
    for (int p = threadIdx.x; p < 512; p += 256) {
        int si = p >> 5, cap = p & 31;
        float d[8];
        float sq = 0.f;
#pragma unroll
        for (int i = 0; i < 8; i++) {
            d[i] = ys[(cap * 8 + i) * 16 + si];
            sq += d[i] * d[i];
        }
        float f = sq / (sqrtf(sq) * (1.f + sq));
        int n = (s0 + si) * 32 + cap;
        float* up = u + ((size_t)b * 25088 + n) * 8;
#pragma unroll
        for (int i = 0; i < 8; i++) up[i] = f * d[i];
    }
}

// ---------------- fused routing pass ----------------
// mode 0: uh from W (fp32), write u_hat fp16, c = 0.1
// mode 1: uh from u_hat fp16; bl = uh.v ; write blog
// mode 2: uh from u_hat fp16; bl = blog + uh.v
__global__ void routing_kernel(const float* __restrict__ W, int mode) {
    int warp = (blockIdx.x * 256 + threadIdx.x) >> 5;
    int lane = threadIdx.x & 31;
    int bhalf = lane >> 4;
    int j = lane & 15;
    float s_acc[4][10];
#pragma unroll
    for (int bp = 0; bp < 4; bp++)
#pragma unroll
        for (int k = 0; k < 10; k++) s_acc[bp][k] = 0.f;

    int n0 = warp * 8;
    for (int nn = 0; nn < 8; nn++) {
        int n = n0 + nn;
        const float* Wn = W + (size_t)n * 1280;
#pragma unroll
        for (int bp = 0; bp < 4; bp++) {
            int b = bp * 2 + bhalf;
            float uh[10];
            if (mode == 0) {
                const float* up = g_u + ((size_t)b * 25088 + n) * 8;
                float uu[8];
#pragma unroll
                for (int i = 0; i < 8; i++) uu[i] = up[i];
#pragma unroll
                for (int k = 0; k < 10; k++) {
                    float a = 0.f;
#pragma unroll
                    for (int i = 0; i < 8; i++) a += uu[i] * Wn[k * 128 + i * 16 + j];
                    uh[k] = a;
                }
                __half* uhp = g_uhath + (((size_t)b * 25088 + n) * 10) * 16 + j;
#pragma unroll
                for (int k = 0; k < 10; k++) uhp[k * 16] = __float2half(uh[k]);
#pragma unroll
                for (int k = 0; k < 10; k++) s_acc[bp][k] += 0.1f * uh[k];
            } else {
                const __half* uhp = g_uhath + (((size_t)b * 25088 + n) * 10) * 16 + j;
#pragma unroll
                for (int k = 0; k < 10; k++) uh[k] = __half2float(uhp[k * 16]);
                float bl[10];
#pragma unroll
                for (int k = 0; k < 10; k++) {
                    float d = uh[k] * g_v[(b * 10 + k) * 16 + j];
                    d += __shfl_xor_sync(0xffffffffu, d, 1);
                    d += __shfl_xor_sync(0xffffffffu, d, 2);
                    d += __shfl_xor_sync(0xffffffffu, d, 4);
                    d += __shfl_xor_sync(0xffffffffu, d, 8);
                    bl[k] = d;
                }
                if (mode == 2) {
#pragma unroll
                    for (int k = 0; k < 10; k++)
                        bl[k] += g_blog[((size_t)b * 25088 + n) * 10 + k];
                } else if (j == 0) {
#pragma unroll
                    for (int k = 0; k < 10; k++)
                        g_blog[((size_t)b * 25088 + n) * 10 + k] = bl[k];
                }
                float m = bl[0];
#pragma unroll
                for (int k = 1; k < 10; k++) m = fmaxf(m, bl[k]);
                float sum = 0.f;
                float c[10];
#pragma unroll
                for (int k = 0; k < 10; k++) { c[k] = __expf(bl[k] - m); sum += c[k]; }
                float inv = 1.f / sum;
#pragma unroll
                for (int k = 0; k < 10; k++) s_acc[bp][k] += c[k] * inv * uh[k];
            }
        }
    }
    __shared__ float ssm[8][1280];
    int wl = (threadIdx.x >> 5);
#pragma unroll
    for (int bp = 0; bp < 4; bp++) {
        int b = bp * 2 + bhalf;
#pragma unroll
        for (int k = 0; k < 10; k++)
            ssm[wl][(b * 10 + k) * 16 + j] = s_acc[bp][k];
    }
    __syncthreads();
    for (int i = threadIdx.x; i < 1280; i += 256) {
        float t = 0.f;
#pragma unroll
        for (int w = 0; w < 8; w++) t += ssm[w][i];
        g_spart[blockIdx.x * 1280 + i] = t;
    }
}

// ---------------- fused reduce + squash ----------------
__global__ void reduce_squash_kernel(float* out_opt) {
    int half = threadIdx.x >> 7;
    int t = threadIdx.x & 127;
    int i = blockIdx.x * 128 + t;  // 10 blocks x 128 = 1280
    float s = 0.f;
    for (int p = half * 196; p < half * 196 + 196; p++) s += g_spart[p * 1280 + i];
    __shared__ float sh[128];
    if (half) sh[t] = s;
    __syncthreads();
    if (!half) {
        s += sh[t];
        float sq = s * s;
        sq += __shfl_xor_sync(0xffffffffu, sq, 1);
        sq += __shfl_xor_sync(0xffffffffu, sq, 2);
        sq += __shfl_xor_sync(0xffffffffu, sq, 4);
        sq += __shfl_xor_sync(0xffffffffu, sq, 8);
        float f = sq / (sqrtf(sq) * (1.f + sq));
        float vv = f * s;
        g_v[i] = vv;
        if (out_opt) out_opt[i] = vv;
    }
}

// ---------------- decoder ----------------
__global__ void fc1_kernel(const float* __restrict__ target,
                           const float* __restrict__ w,
                           const float* __restrict__ bias) {
    int b = blockIdx.x;
    __shared__ float vm[16];
    if (threadIdx.x < 16) {
        float a = 0.f;
        for (int k = 0; k < 10; k++) a += target[b * 10 + k] * g_v[(b * 10 + k) * 16 + threadIdx.x];
        vm[threadIdx.x] = a;
    }
    __syncthreads();
    int o = threadIdx.x;
    float acc = bias[o];
#pragma unroll
    for (int i = 0; i < 16; i++) acc += vm[i] * w[o * 16 + i];
    g_h1[b * 512 + o] = fmaxf(acc, 0.f);
}

// fc2: grid (8 oslice, 8 b), 256 thr; warp-per-output, 16 outputs/warp
__global__ void fc2_kernel(const float* __restrict__ w, const float* __restrict__ bias) {
    int osl = blockIdx.x, b = blockIdx.y;
    __shared__ float h1[512];
    for (int i = threadIdx.x; i < 512; i += 256) h1[i] = g_h1[b * 512 + i];
    __syncthreads();
    int warp = threadIdx.x >> 5, lane = threadIdx.x & 31;
    for (int k = 0; k < 16; k++) {
        int o = osl * 128 + warp * 16 + k;
        const float* wr = w + (size_t)o * 512;
        float a = 0.f;
#pragma unroll
        for (int i = lane; i < 512; i += 32) a += h1[i] * wr[i];
        a += __shfl_xor_sync(0xffffffffu, a, 16);
        a += __shfl_xor_sync(0xffffffffu, a, 8);
        a += __shfl_xor_sync(0xffffffffu, a, 4);
        a += __shfl_xor_sync(0xffffffffu, a, 2);
        a += __shfl_xor_sync(0xffffffffu, a, 1);
        if (lane == 0) g_h2[b * 1024 + o] = fmaxf(a + bias[o], 0.f);
    }
}

// fc3: grid (9 oslice, 8 b), 256 thr; warp-per-output, 18 outputs/warp
__global__ void fc3_kernel(const float* __restrict__ w, const float* __restrict__ bias) {
    int osl = blockIdx.x, b = blockIdx.y;
    __shared__ float h2[1024];
    for (int i = threadIdx.x; i < 1024; i += 256) h2[i] = g_h2[b * 1024 + i];
    __syncthreads();
    int warp = threadIdx.x >> 5, lane = threadIdx.x & 31;
    for (int k = 0; k < 18; k++) {
        int o = osl * 144 + warp * 18 + k;
        const float* wr = w + (size_t)o * 1024;
        float a = 0.f;
#pragma unroll
        for (int i = lane; i < 1024; i += 32) a += h2[i] * wr[i];
        a += __shfl_xor_sync(0xffffffffu, a, 16);
        a += __shfl_xor_sync(0xffffffffu, a, 8);
        a += __shfl_xor_sync(0xffffffffu, a, 4);
        a += __shfl_xor_sync(0xffffffffu, a, 2);
        a += __shfl_xor_sync(0xffffffffu, a, 1);
        if (lane == 0) g_rec[b * 1296 + o] = 1.f / (1.f + __expf(-(a + bias[o])));
    }
}

__global__ void upsample_kernel(float* __restrict__ out) {
    int idx = blockIdx.x * 256 + threadIdx.x;
    if (idx >= 8 * 5184) return;
    int b = idx / 5184;
    int r = idx - b * 5184;
    int oy = r / 72, ox = r - oy * 72;
    float sy = (float)(oy * 35) / 71.0f;
    float sx = (float)(ox * 35) / 71.0f;
    int y0 = (int)sy, x0 = (int)sx;
    int y1 = min(y0 + 1, 35), x1 = min(x0 + 1, 35);
    float wy = sy - (float)y0, wx = sx - (float)x0;
    const float* rb = g_rec + b * 1296;
    float a00 = rb[y0 * 36 + x0], a01 = rb[y0 * 36 + x1];
    float a10 = rb[y1 * 36 + x0], a11 = rb[y1 * 36 + x1];
    float v = (1.f - wy) * ((1.f - wx) * a00 + wx * a01) +
              wy * ((1.f - wx) * a10 + wx * a11);
    out[1280 + b * 5184 + r] = v;
}

// ---------------- launch ----------------
extern "C" void kernel_launch(void* const* d_in, const int* in_sizes, int n_in,
                              void* d_out, int out_size) {
    const float* x       = (const float*)d_in[0];
    const float* target  = (const float*)d_in[1];
    const float* conv1_w = (const float*)d_in[2];
    const float* conv1_b = (const float*)d_in[3];
    const float* pc1_w   = (const float*)d_in[4];
    const float* pc1_b   = (const float*)d_in[5];
    const float* pc2_w   = (const float*)d_in[6];
    const float* pc2_b   = (const float*)d_in[7];
    const float* pc3_w   = (const float*)d_in[8];
    const float* pc3_b   = (const float*)d_in[9];
    const float* W_digit = (const float*)d_in[10];
    const float* fc1_w   = (const float*)d_in[11];
    const float* fc1_b   = (const float*)d_in[12];
    const float* fc2_w   = (const float*)d_in[13];
    const float* fc2_b   = (const float*)d_in[14];
    const float* fc3_w   = (const float*)d_in[15];
    const float* fc3_b   = (const float*)d_in[16];
    float* out = (float*)d_out;

    float *pc1p, *pc2p, *pc3p, *up;
    __half *conv1p, *wpp, *bmp;
    cudaGetSymbolAddress((void**)&conv1p, g_conv1h);
    cudaGetSymbolAddress((void**)&wpp, g_wpadh);
    cudaGetSymbolAddress((void**)&bmp, g_bmat);
    cudaGetSymbolAddress((void**)&pc1p, g_pc1);
    cudaGetSymbolAddress((void**)&pc2p, g_pc2);
    cudaGetSymbolAddress((void**)&pc3p, g_pc3);
    cudaGetSymbolAddress((void**)&up, g_u);

    conv1_kernel<<<dim3(256, 8), 256>>>(x, conv1_w, conv1_b, conv1p);
    wpad_kernel<<<12800, 256>>>(pc1_w, wpp);
    im2col_kernel<<<dim3(30, 4, 8), 256>>>(conv1p, bmp);
    pc1_mma_kernel<<<dim3(8, 4, 8), 256>>>(bmp, (const uint4*)wpp, pc1_b, pc1p);
    pc2_kernel<<<dim3(32, 8, 3), 256>>>(pc1p, pc2_w, pc2_b, pc2p);
    pc3_kernel<<<dim3(32, 8, 4), 256>>>(pc2p, pc3_w, pc3_b, pc3p);
    u_build_kernel<<<dim3(49, 8), 256>>>(pc3p, up);

    // routing
    routing_kernel<<<392, 256>>>(W_digit, 0);
    reduce_squash_kernel<<<10, 256>>>(nullptr);
    routing_kernel<<<392, 256>>>(W_digit, 1);
    reduce_squash_kernel<<<10, 256>>>(nullptr);
    routing_kernel<<<392, 256>>>(W_digit, 2);
    reduce_squash_kernel<<<10, 256>>>(out);

    // decoder
    fc1_kernel<<<8, 512>>>(target, fc1_w, fc1_b);
    fc2_kernel<<<dim3(8, 8), 256>>>(fc2_w, fc2_b);
    fc3_kernel<<<dim3(9, 8), 256>>>(fc3_w, fc3_b);
    upsample_kernel<<<162, 256>>>(out);
}

// round 14
// speedup vs baseline: 1.7945x; 1.0198x over previous
#include <cuda_runtime.h>
#include <cuda_fp16.h>
#include <math.h>
#include <stdint.h>

// ---------------- scratch (static __device__, no allocations) ----------------
__device__ __align__(16) __half g_conv1h[8 * 256 * 64 * 64]; // [b][oc][64*64] fp16
__device__ __align__(16) __half g_wpadh[512 * 6400];         // pc1 weights fp16, dense K
__device__ __align__(16) __half g_bmat[8 * 900 * 6400];      // im2col [b][sp][k] fp16 dense
__device__ __align__(16) __half g_uhath[(size_t)8 * 25088 * 10 * 16]; // u_hat fp16
__device__ float g_pc1[8 * 512 * 900];         // [b][oc][30*30]
__device__ float g_pc2[8 * 256 * 900];
__device__ float g_pc3[8 * 256 * 784];         // [b][oc][28*28]
__device__ float g_u[8 * 25088 * 8];           // squashed primary caps
__device__ float g_blog[8 * 25088 * 10];       // routing logits
__device__ float g_spart[392 * 1280];          // per-block partial s
__device__ float g_v[1280];
__device__ float g_h1[8 * 512];
__device__ float g_h2[8 * 1024];
__device__ float g_rec[8 * 1296];

__device__ __forceinline__ void mma_fp16_16x8x16(float* d, const uint32_t* a,
                                                 uint32_t b0, uint32_t b1) {
    asm volatile(
        "mma.sync.aligned.m16n8k16.row.col.f32.f16.f16.f32 "
        "{%0,%1,%2,%3}, {%4,%5,%6,%7}, {%8,%9}, {%0,%1,%2,%3};"
        : "+f"(d[0]), "+f"(d[1]), "+f"(d[2]), "+f"(d[3])
        : "r"(a[0]), "r"(a[1]), "r"(a[2]), "r"(a[3]), "r"(b0), "r"(b1));
}
#define LDSM4(r0, r1, r2, r3, addr)                                         \
    asm volatile("ldmatrix.sync.aligned.m8n8.x4.shared.b16 {%0,%1,%2,%3}, [%4];" \
                 : "=r"(r0), "=r"(r1), "=r"(r2), "=r"(r3) : "r"(addr))
__device__ __forceinline__ void cp_async16(uint32_t dst, const void* src, int srcsize) {
    asm volatile("cp.async.cg.shared.global [%0], [%1], 16, %2;"
                 :: "r"(dst), "l"(src), "r"(srcsize) : "memory");
}
#define CP_COMMIT() asm volatile("cp.async.commit_group;" ::: "memory")

// ---------------- conv1: 1->256ch, 9x9, relu, fp16 out (register-tiled) ----------------
__global__ void conv1_kernel(const float* __restrict__ x,
                             const float* __restrict__ w,
                             const float* __restrict__ bias,
                             __half* __restrict__ out) {
    int oc = blockIdx.x, b = blockIdx.y;
    __shared__ float xs[72 * 72];
    __shared__ float wsh[81];
    for (int i = threadIdx.x; i < 5184; i += 256) xs[i] = x[b * 5184 + i];
    if (threadIdx.x < 81) wsh[threadIdx.x] = w[oc * 81 + threadIdx.x];
    __syncthreads();
    float bv = bias[oc];
    int og = threadIdx.x & 7;
    int r0 = threadIdx.x >> 3;
    __half* ob = out + ((size_t)(b * 256 + oc)) * 4096;
    for (int hf = 0; hf < 2; hf++) {
        int oh = r0 + hf * 32;
        int ow0 = og * 8;
        float acc[8];
#pragma unroll
        for (int o = 0; o < 8; o++) acc[o] = bv;
#pragma unroll
        for (int kh = 0; kh < 9; kh++) {
            const float* row = &xs[(oh + kh) * 72 + ow0];
            float seg[16];
#pragma unroll
            for (int s = 0; s < 16; s += 4) {
                float4 v = *(const float4*)&row[s];
                seg[s] = v.x; seg[s + 1] = v.y; seg[s + 2] = v.z; seg[s + 3] = v.w;
            }
#pragma unroll
            for (int kw = 0; kw < 9; kw++) {
                float wv = wsh[kh * 9 + kw];
#pragma unroll
                for (int o = 0; o < 8; o++) acc[o] += seg[kw + o] * wv;
            }
        }
#pragma unroll
        for (int o = 0; o < 8; o++)
            ob[oh * 64 + ow0 + o] = __float2half(fmaxf(acc[o], 0.f));
    }
}

// ---------------- pc1 weight prep: dense fp16 copy [512][6400] ----------------
__global__ void wpad_kernel(const float* __restrict__ w, __half* __restrict__ wp) {
    int idx = blockIdx.x * 256 + threadIdx.x;
    if (idx < 512 * 6400) wp[idx] = __float2half(w[idx]);
}

// ---------------- im2col dense: conv1h -> Bmat[b][sp][k], k = ic*25+e ----------------
__global__ void im2col_kernel(const __half* __restrict__ ch, __half* __restrict__ bm) {
    int oh = blockIdx.x, icc = blockIdx.y, b = blockIdx.z;
    __shared__ __half sx[64 * 324];
    const __half* src = ch + ((size_t)(b * 256 + icc * 64)) * 4096 + (2 * oh) * 64;
    for (int idx = threadIdx.x; idx < 5120; idx += 256) {
        int c4 = idx & 15;
        int r = (idx >> 4) % 5;
        int ic = idx / 80;
        *(uint2*)&sx[ic * 324 + r * 64 + c4 * 4] =
            *(const uint2*)&src[(size_t)ic * 4096 + r * 64 + c4 * 4];
    }
    __syncthreads();
    __half* dstb = bm + ((size_t)b * 900 + oh * 30) * 6400 + icc * 1600;
    for (int idx = threadIdx.x; idx < 1500; idx += 256) {
        int ow = idx % 30;
        int kc = idx / 30;
        int kl = kc * 32;
        int ic = kl / 25;
        int e = kl - ic * 25;
        __half hv[32];
#pragma unroll
        for (int kk = 0; kk < 32; kk++) {
            hv[kk] = sx[ic * 324 + (e / 5) * 64 + 2 * ow + (e % 5)];
            if (++e == 25) { e = 0; ic++; }
        }
        uint32_t pk[16];
#pragma unroll
        for (int t = 0; t < 16; t++) {
            __half2 p = __halves2half2(hv[2 * t], hv[2 * t + 1]);
            pk[t] = *(uint32_t*)&p;
        }
        uint4* dst = (uint4*)(dstb + (size_t)ow * 6400 + kl);
        dst[0] = make_uint4(pk[0], pk[1], pk[2], pk[3]);
        dst[1] = make_uint4(pk[4], pk[5], pk[6], pk[7]);
        dst[2] = make_uint4(pk[8], pk[9], pk[10], pk[11]);
        dst[3] = make_uint4(pk[12], pk[13], pk[14], pk[15]);
    }
}

// ---------------- pc1: mma.sync fp16, 3-stage cp.async pipeline (1 barrier/chunk) ----------------
#define ASTR 40     // halves per row (80B) -> conflict-free ldmatrix rows
#define KCH 200     // K chunks of 32
#define RSTR 800    // row stride in uint4 (6400 halves)
#define STG_B 20480 // bytes per stage (A 10240 + B 10240)
__global__ void __launch_bounds__(256, 2)
pc1_mma_kernel(const __half* __restrict__ bmat, const uint4* __restrict__ wph4,
               const float* __restrict__ bias, float* __restrict__ out) {
    extern __shared__ __align__(16) __half smemBuf[];  // 3 * STG_B bytes
    const int tid = threadIdx.x;
    const int lane = tid & 31, wid = tid >> 5;
    const int spt = blockIdx.x, oct = blockIdx.y, b = blockIdx.z;
    const int oc_base = oct * 128, sp_base = spt * 128;
    const int wm = wid & 3, wn = wid >> 2;
    const uint32_t sb = (uint32_t)__cvta_generic_to_shared(smemBuf);

    // producer geometry: thread covers rows rr2, rr2+64 at 16B group grp4
    const int grp4 = tid & 3;
    const int rr2 = tid >> 2;  // 0..63
    const uint4* bb[2];
    int bsz[2];
#pragma unroll
    for (int q = 0; q < 2; q++) {
        int sp = sp_base + rr2 + 64 * q;
        bsz[q] = (sp < 900) ? 16 : 0;
        bb[q] = (const uint4*)(bmat + ((size_t)b * 900 + (sp < 900 ? sp : 0)) * 6400) + grp4;
    }
    const uint4* wbase = wph4 + (size_t)oc_base * RSTR + grp4;

    uint32_t dOff[2];  // per-thread dst byte offset within a stage tile
#pragma unroll
    for (int q = 0; q < 2; q++)
        dOff[q] = ((rr2 + 64 * q) * ASTR + grp4 * 8) * 2;

    float acc[2][8][4];
#pragma unroll
    for (int mt = 0; mt < 2; mt++)
#pragma unroll
        for (int nt = 0; nt < 8; nt++)
#pragma unroll
            for (int i = 0; i < 4; i++) acc[mt][nt][i] = 0.f;

    // ldmatrix per-lane address offsets (bytes within a stage tile)
    const int l15 = lane & 15;
    uint32_t a_off[2];
#pragma unroll
    for (int mt = 0; mt < 2; mt++)
        a_off[mt] = (uint32_t)(((wm * 2 + mt) * 16 + l15) * ASTR + ((lane >> 4) & 1) * 8) * 2;
    uint32_t b_off[4];
#pragma unroll
    for (int p = 0; p < 4; p++)
        b_off[p] = (uint32_t)((((wn * 8 + 2 * p + ((lane >> 4) & 1)) * 8) + (lane & 7)) * ASTR +
                              ((lane >> 3) & 1) * 8) * 2;

    // prologue: chunks 0,1 into stages 0,1
#pragma unroll
    for (int c = 0; c < 2; c++) {
        uint32_t stA = sb + c * STG_B;
        uint32_t stB = stA + 10240;
#pragma unroll
        for (int q = 0; q < 2; q++)
            cp_async16(stA + dOff[q], wbase + (size_t)(rr2 + 64 * q) * RSTR + c * 4, 16);
#pragma unroll
        for (int q = 0; q < 2; q++)
            cp_async16(stB + dOff[q], bb[q] + c * 4, bsz[q]);
        CP_COMMIT();
    }

    int st = 0;  // stage of chunk ic
    for (int ic = 0; ic < KCH; ic++) {
        if (ic == KCH - 1)
            asm volatile("cp.async.wait_group 0;" ::: "memory");
        else
            asm volatile("cp.async.wait_group 1;" ::: "memory");
        __syncthreads();
        // prefetch chunk ic+2 into the stage last read at ic-1 (safe after the sync)
        if (ic + 2 < KCH) {
            int s2 = st + 2;
            if (s2 >= 3) s2 -= 3;
            uint32_t stA = sb + s2 * STG_B;
            uint32_t stB = stA + 10240;
#pragma unroll
            for (int q = 0; q < 2; q++)
                cp_async16(stA + dOff[q], wbase + (size_t)(rr2 + 64 * q) * RSTR + (ic + 2) * 4, 16);
#pragma unroll
            for (int q = 0; q < 2; q++)
                cp_async16(stB + dOff[q], bb[q] + (ic + 2) * 4, bsz[q]);
            CP_COMMIT();
        }
        const uint32_t aBase = sb + st * STG_B;
        const uint32_t bBase = aBase + 10240;
#pragma unroll
        for (int k16 = 0; k16 < 2; k16++) {
            const uint32_t kadd = k16 * 32;  // bytes (16 halves)
            uint32_t afr[2][4];
            LDSM4(afr[0][0], afr[0][1], afr[0][2], afr[0][3], aBase + a_off[0] + kadd);
            LDSM4(afr[1][0], afr[1][1], afr[1][2], afr[1][3], aBase + a_off[1] + kadd);
#pragma unroll
            for (int p = 0; p < 4; p++) {
                uint32_t b0, b1, b2, b3;
                LDSM4(b0, b1, b2, b3, bBase + b_off[p] + kadd);
                mma_fp16_16x8x16(acc[0][2 * p], afr[0], b0, b1);
                mma_fp16_16x8x16(acc[1][2 * p], afr[1], b0, b1);
                mma_fp16_16x8x16(acc[0][2 * p + 1], afr[0], b2, b3);
                mma_fp16_16x8x16(acc[1][2 * p + 1], afr[1], b2, b3);
            }
        }
        if (++st == 3) st = 0;
    }
    // epilogue
    const int gr = lane >> 2;
    const int c2 = (lane & 3) * 2;
#pragma unroll
    for (int mt = 0; mt < 2; mt++) {
        int oc0 = oc_base + (wm * 2 + mt) * 16 + gr;
        float b0 = bias[oc0], b1 = bias[oc0 + 8];
        float* op0 = out + ((size_t)b * 512 + oc0) * 900;
        float* op1 = out + ((size_t)b * 512 + oc0 + 8) * 900;
#pragma unroll
        for (int nt = 0; nt < 8; nt++) {
            int sp = sp_base + (wn * 8 + nt) * 8 + c2;
            if (sp < 900) {
                *(float2*)&op0[sp] = make_float2(acc[mt][nt][0] + b0, acc[mt][nt][1] + b0);
                *(float2*)&op1[sp] = make_float2(acc[mt][nt][2] + b1, acc[mt][nt][3] + b1);
            }
        }
    }
}

// ---------------- pc2: grouped 32g, 16->8, 3x3, pad 1 (5 row slices) ----------------
__global__ void pc2_kernel(const float* __restrict__ in,
                           const float* __restrict__ w,
                           const float* __restrict__ bias,
                           float* __restrict__ out) {
    int g = blockIdx.x, b = blockIdx.y, sl = blockIdx.z;
    int oh0 = sl * 6;
    __shared__ float wsh[1152];
    __shared__ float xin[16 * 8 * 30];
    for (int idx = threadIdx.x; idx < 1152; idx += 256) wsh[idx] = w[g * 1152 + idx];
    const float* inb = in + ((size_t)b * 512 + g * 16) * 900;
    for (int idx = threadIdx.x; idx < 3840; idx += 256) {
        int iw = idx % 30;
        int r2 = idx / 30;
        int ihl = r2 % 8, i = r2 / 8;
        int ih = oh0 - 1 + ihl;
        xin[idx] = (ih >= 0 && ih < 30) ? inb[i * 900 + ih * 30 + iw] : 0.f;
    }
    __syncthreads();
    for (int spl = threadIdx.x; spl < 180; spl += 256) {
        int ohl = spl / 30, ow = spl - ohl * 30;
        int oh = oh0 + ohl;
        float acc[8];
#pragma unroll
        for (int o = 0; o < 8; o++) acc[o] = bias[g * 8 + o];
        for (int i = 0; i < 16; i++) {
            const float* ip = xin + i * 240;
#pragma unroll
            for (int kh = 0; kh < 3; kh++) {
#pragma unroll
                for (int kw = 0; kw < 3; kw++) {
                    int iw = ow - 1 + kw;
                    if (iw < 0 || iw >= 30) continue;
                    float v = ip[(ohl + kh) * 30 + iw];
                    int e = kh * 3 + kw;
#pragma unroll
                    for (int o = 0; o < 8; o++) acc[o] += v * wsh[(o * 16 + i) * 9 + e];
                }
            }
        }
#pragma unroll
        for (int o = 0; o < 8; o++)
            out[((size_t)b * 256 + g * 8 + o) * 900 + oh * 30 + ow] = acc[o];
    }
}

// ---------------- pc3: grouped 32g, 8->8, 3x3, pad 0 (30->28), 4 row slices ----------------
__global__ void pc3_kernel(const float* __restrict__ in,
                           const float* __restrict__ w,
                           const float* __restrict__ bias,
                           float* __restrict__ out) {
    int g = blockIdx.x, b = blockIdx.y, sl = blockIdx.z;
    int oh0 = sl * 7;
    __shared__ float wsh[576];
    __shared__ float xin[8 * 9 * 30];
    for (int idx = threadIdx.x; idx < 576; idx += 256) wsh[idx] = w[g * 576 + idx];
    const float* inb = in + ((size_t)b * 256 + g * 8) * 900;
    for (int idx = threadIdx.x; idx < 2160; idx += 256) {
        int iw = idx % 30;
        int r2 = idx / 30;
        int ihl = r2 % 9, i = r2 / 9;
        xin[idx] = inb[i * 900 + (oh0 + ihl) * 30 + iw];
    }
    __syncthreads();
    for (int spl = threadIdx.x; spl < 196; spl += 256) {
        int ohl = spl / 28, ow = spl - ohl * 28;
        int oh = oh0 + ohl;
        float acc[8];
#pragma unroll
        for (int o = 0; o < 8; o++) acc[o] = bias[g * 8 + o];
        for (int i = 0; i < 8; i++) {
            const float* ip = xin + i * 270;
#pragma unroll
            for (int kh = 0; kh < 3; kh++) {
#pragma unroll
                for (int kw = 0; kw < 3; kw++) {
                    float v = ip[(ohl + kh) * 30 + ow + kw];
                    int e = kh * 3 + kw;
#pragma unroll
                    for (int o = 0; o < 8; o++) acc[o] += v * wsh[(o * 8 + i) * 9 + e];
                }
            }
        }
#pragma unroll
        for (int o = 0; o < 8; o++)
            out[((size_t)b * 256 + g * 8 + o) * 784 + oh * 28 + ow] = acc[o];
    }
}

// ---------------- build u (capsule transpose) + squash over dim 8 ----------------
__global__ void u_build_kernel(const float* __restrict__ y, float* __restrict__ u) {
    int b = blockIdx.y;
    int s0 = blockIdx.x * 16;
    __shared__ float ys[256 * 16];
    for (int i = threadIdx.x; i < 4096; i += 256) {
        int ch = i >> 4, si = i & 15;
        ys[i] = y[(b * 256 + ch) * 784 + s0 + si];
    }
    __syncthreads();
    for (int p = threadIdx.x; p < 512; p += 256) {
        int si = p >> 5, cap = p & 31;
        float d[8];
        float sq = 0.f;
#pragma unroll
        for (int i = 0; i < 8; i++) {
            d[i] = ys[(cap * 8 + i) * 16 + si];
            sq += d[i] * d[i];
        }
        float f = sq / (sqrtf(sq) * (1.f + sq));
        int n = (s0 + si) * 32 + cap;
        float* up = u + ((size_t)b * 25088 + n) * 8;
#pragma unroll
        for (int i = 0; i < 8; i++) up[i] = f * d[i];
    }
}

// ---------------- fused routing pass ----------------
// mode 0: uh from W (fp32), write u_hat fp16, c = 0.1
// mode 1: uh from u_hat fp16; bl = uh.v ; write blog
// mode 2: uh from u_hat fp16; bl = blog + uh.v
__global__ void routing_kernel(const float* __restrict__ W, int mode) {
    int warp = (blockIdx.x * 256 + threadIdx.x) >> 5;
    int lane = threadIdx.x & 31;
    int bhalf = lane >> 4;
    int j = lane & 15;
    float s_acc[4][10];
#pragma unroll
    for (int bp = 0; bp < 4; bp++)
#pragma unroll
        for (int k = 0; k < 10; k++) s_acc[bp][k] = 0.f;

    int n0 = warp * 8;
    for (int nn = 0; nn < 8; nn++) {
        int n = n0 + nn;
        const float* Wn = W + (size_t)n * 1280;
#pragma unroll
        for (int bp = 0; bp < 4; bp++) {
            int b = bp * 2 + bhalf;
            float uh[10];
            if (mode == 0) {
                const float* up = g_u + ((size_t)b * 25088 + n) * 8;
                float uu[8];
#pragma unroll
                for (int i = 0; i < 8; i++) uu[i] = up[i];
#pragma unroll
                for (int k = 0; k < 10; k++) {
                    float a = 0.f;
#pragma unroll
                    for (int i = 0; i < 8; i++) a += uu[i] * Wn[k * 128 + i * 16 + j];
                    uh[k] = a;
                }
                __half* uhp = g_uhath + (((size_t)b * 25088 + n) * 10) * 16 + j;
#pragma unroll
                for (int k = 0; k < 10; k++) uhp[k * 16] = __float2half(uh[k]);
#pragma unroll
                for (int k = 0; k < 10; k++) s_acc[bp][k] += 0.1f * uh[k];
            } else {
                const __half* uhp = g_uhath + (((size_t)b * 25088 + n) * 10) * 16 + j;
#pragma unroll
                for (int k = 0; k < 10; k++) uh[k] = __half2float(uhp[k * 16]);
                float bl[10];
#pragma unroll
                for (int k = 0; k < 10; k++) {
                    float d = uh[k] * g_v[(b * 10 + k) * 16 + j];
                    d += __shfl_xor_sync(0xffffffffu, d, 1);
                    d += __shfl_xor_sync(0xffffffffu, d, 2);
                    d += __shfl_xor_sync(0xffffffffu, d, 4);
                    d += __shfl_xor_sync(0xffffffffu, d, 8);
                    bl[k] = d;
                }
                if (mode == 2) {
#pragma unroll
                    for (int k = 0; k < 10; k++)
                        bl[k] += g_blog[((size_t)b * 25088 + n) * 10 + k];
                } else if (j == 0) {
#pragma unroll
                    for (int k = 0; k < 10; k++)
                        g_blog[((size_t)b * 25088 + n) * 10 + k] = bl[k];
                }
                float m = bl[0];
#pragma unroll
                for (int k = 1; k < 10; k++) m = fmaxf(m, bl[k]);
                float sum = 0.f;
                float c[10];
#pragma unroll
                for (int k = 0; k < 10; k++) { c[k] = __expf(bl[k] - m); sum += c[k]; }
                float inv = 1.f / sum;
#pragma unroll
                for (int k = 0; k < 10; k++) s_acc[bp][k] += c[k] * inv * uh[k];
            }
        }
    }
    __shared__ float ssm[8][1280];
    int wl = (threadIdx.x >> 5);
#pragma unroll
    for (int bp = 0; bp < 4; bp++) {
        int b = bp * 2 + bhalf;
#pragma unroll
        for (int k = 0; k < 10; k++)
            ssm[wl][(b * 10 + k) * 16 + j] = s_acc[bp][k];
    }
    __syncthreads();
    for (int i = threadIdx.x; i < 1280; i += 256) {
        float t = 0.f;
#pragma unroll
        for (int w = 0; w < 8; w++) t += ssm[w][i];
        g_spart[blockIdx.x * 1280 + i] = t;
    }
}

// ---------------- fused reduce + squash ----------------
__global__ void reduce_squash_kernel(float* out_opt) {
    int half = threadIdx.x >> 7;
    int t = threadIdx.x & 127;
    int i = blockIdx.x * 128 + t;  // 10 blocks x 128 = 1280
    float s = 0.f;
    for (int p = half * 196; p < half * 196 + 196; p++) s += g_spart[p * 1280 + i];
    __shared__ float sh[128];
    if (half) sh[t] = s;
    __syncthreads();
    if (!half) {
        s += sh[t];
        float sq = s * s;
        sq += __shfl_xor_sync(0xffffffffu, sq, 1);
        sq += __shfl_xor_sync(0xffffffffu, sq, 2);
        sq += __shfl_xor_sync(0xffffffffu, sq, 4);
        sq += __shfl_xor_sync(0xffffffffu, sq, 8);
        float f = sq / (sqrtf(sq) * (1.f + sq));
        float vv = f * s;
        g_v[i] = vv;
        if (out_opt) out_opt[i] = vv;
    }
}

// ---------------- decoder ----------------
__global__ void fc1_kernel(const float* __restrict__ target,
                           const float* __restrict__ w,
                           const float* __restrict__ bias) {
    int b = blockIdx.x;
    __shared__ float vm[16];
    if (threadIdx.x < 16) {
        float a = 0.f;
        for (int k = 0; k < 10; k++) a += target[b * 10 + k] * g_v[(b * 10 + k) * 16 + threadIdx.x];
        vm[threadIdx.x] = a;
    }
    __syncthreads();
    int o = threadIdx.x;
    float acc = bias[o];
#pragma unroll
    for (int i = 0; i < 16; i++) acc += vm[i] * w[o * 16 + i];
    g_h1[b * 512 + o] = fmaxf(acc, 0.f);
}

// fc2: grid (8 oslice, 8 b), 256 thr; warp-per-output, 16 outputs/warp
__global__ void fc2_kernel(const float* __restrict__ w, const float* __restrict__ bias) {
    int osl = blockIdx.x, b = blockIdx.y;
    __shared__ float h1[512];
    for (int i = threadIdx.x; i < 512; i += 256) h1[i] = g_h1[b * 512 + i];
    __syncthreads();
    int warp = threadIdx.x >> 5, lane = threadIdx.x & 31;
    for (int k = 0; k < 16; k++) {
        int o = osl * 128 + warp * 16 + k;
        const float* wr = w + (size_t)o * 512;
        float a = 0.f;
#pragma unroll
        for (int i = lane; i < 512; i += 32) a += h1[i] * wr[i];
        a += __shfl_xor_sync(0xffffffffu, a, 16);
        a += __shfl_xor_sync(0xffffffffu, a, 8);
        a += __shfl_xor_sync(0xffffffffu, a, 4);
        a += __shfl_xor_sync(0xffffffffu, a, 2);
        a += __shfl_xor_sync(0xffffffffu, a, 1);
        if (lane == 0) g_h2[b * 1024 + o] = fmaxf(a + bias[o], 0.f);
    }
}

// fc3: grid (9 oslice, 8 b), 256 thr; warp-per-output, 18 outputs/warp
__global__ void fc3_kernel(const float* __restrict__ w, const float* __restrict__ bias) {
    int osl = blockIdx.x, b = blockIdx.y;
    __shared__ float h2[1024];
    for (int i = threadIdx.x; i < 1024; i += 256) h2[i] = g_h2[b * 1024 + i];
    __syncthreads();
    int warp = threadIdx.x >> 5, lane = threadIdx.x & 31;
    for (int k = 0; k < 18; k++) {
        int o = osl * 144 + warp * 18 + k;
        const float* wr = w + (size_t)o * 1024;
        float a = 0.f;
#pragma unroll
        for (int i = lane; i < 1024; i += 32) a += h2[i] * wr[i];
        a += __shfl_xor_sync(0xffffffffu, a, 16);
        a += __shfl_xor_sync(0xffffffffu, a, 8);
        a += __shfl_xor_sync(0xffffffffu, a, 4);
        a += __shfl_xor_sync(0xffffffffu, a, 2);
        a += __shfl_xor_sync(0xffffffffu, a, 1);
        if (lane == 0) g_rec[b * 1296 + o] = 1.f / (1.f + __expf(-(a + bias[o])));
    }
}

__global__ void upsample_kernel(float* __restrict__ out) {
    int idx = blockIdx.x * 256 + threadIdx.x;
    if (idx >= 8 * 5184) return;
    int b = idx / 5184;
    int r = idx - b * 5184;
    int oy = r / 72, ox = r - oy * 72;
    float sy = (float)(oy * 35) / 71.0f;
    float sx = (float)(ox * 35) / 71.0f;
    int y0 = (int)sy, x0 = (int)sx;
    int y1 = min(y0 + 1, 35), x1 = min(x0 + 1, 35);
    float wy = sy - (float)y0, wx = sx - (float)x0;
    const float* rb = g_rec + b * 1296;
    float a00 = rb[y0 * 36 + x0], a01 = rb[y0 * 36 + x1];
    float a10 = rb[y1 * 36 + x0], a11 = rb[y1 * 36 + x1];
    float v = (1.f - wy) * ((1.f - wx) * a00 + wx * a01) +
              wy * ((1.f - wx) * a10 + wx * a11);
    out[1280 + b * 5184 + r] = v;
}

// ---------------- launch ----------------
extern "C" void kernel_launch(void* const* d_in, const int* in_sizes, int n_in,
                              void* d_out, int out_size) {
    const float* x       = (const float*)d_in[0];
    const float* target  = (const float*)d_in[1];
    const float* conv1_w = (const float*)d_in[2];
    const float* conv1_b = (const float*)d_in[3];
    const float* pc1_w   = (const float*)d_in[4];
    const float* pc1_b   = (const float*)d_in[5];
    const float* pc2_w   = (const float*)d_in[6];
    const float* pc2_b   = (const float*)d_in[7];
    const float* pc3_w   = (const float*)d_in[8];
    const float* pc3_b   = (const float*)d_in[9];
    const float* W_digit = (const float*)d_in[10];
    const float* fc1_w   = (const float*)d_in[11];
    const float* fc1_b   = (const float*)d_in[12];
    const float* fc2_w   = (const float*)d_in[13];
    const float* fc2_b   = (const float*)d_in[14];
    const float* fc3_w   = (const float*)d_in[15];
    const float* fc3_b   = (const float*)d_in[16];
    float* out = (float*)d_out;

    float *pc1p, *pc2p, *pc3p, *up;
    __half *conv1p, *wpp, *bmp;
    cudaGetSymbolAddress((void**)&conv1p, g_conv1h);
    cudaGetSymbolAddress((void**)&wpp, g_wpadh);
    cudaGetSymbolAddress((void**)&bmp, g_bmat);
    cudaGetSymbolAddress((void**)&pc1p, g_pc1);
    cudaGetSymbolAddress((void**)&pc2p, g_pc2);
    cudaGetSymbolAddress((void**)&pc3p, g_pc3);
    cudaGetSymbolAddress((void**)&up, g_u);

    cudaFuncSetAttribute(pc1_mma_kernel, cudaFuncAttributeMaxDynamicSharedMemorySize, 61440);

    conv1_kernel<<<dim3(256, 8), 256>>>(x, conv1_w, conv1_b, conv1p);
    wpad_kernel<<<12800, 256>>>(pc1_w, wpp);
    im2col_kernel<<<dim3(30, 4, 8), 256>>>(conv1p, bmp);
    pc1_mma_kernel<<<dim3(8, 4, 8), 256, 61440>>>(bmp, (const uint4*)wpp, pc1_b, pc1p);
    pc2_kernel<<<dim3(32, 8, 5), 256>>>(pc1p, pc2_w, pc2_b, pc2p);
    pc3_kernel<<<dim3(32, 8, 4), 256>>>(pc2p, pc3_w, pc3_b, pc3p);
    u_build_kernel<<<dim3(49, 8), 256>>>(pc3p, up);

    // routing
    routing_kernel<<<392, 256>>>(W_digit, 0);
    reduce_squash_kernel<<<10, 256>>>(nullptr);
    routing_kernel<<<392, 256>>>(W_digit, 1);
    reduce_squash_kernel<<<10, 256>>>(nullptr);
    routing_kernel<<<392, 256>>>(W_digit, 2);
    reduce_squash_kernel<<<10, 256>>>(out);

    // decoder
    fc1_kernel<<<8, 512>>>(target, fc1_w, fc1_b);
    fc2_kernel<<<dim3(8, 8), 256>>>(fc2_w, fc2_b);
    fc3_kernel<<<dim3(9, 8), 256>>>(fc3_w, fc3_b);
    upsample_kernel<<<162, 256>>>(out);
}